// round 10
// baseline (speedup 1.0000x reference)
#include <cuda_runtime.h>
#include <cuda_bf16.h>
#include <cstdint>

#define NN 100000
#define NE 1600000
#define HID 128
#define EMB_W 640
#define SCAN_B 98
#define GRID_M 1563           // ceil(NN/64)

// ---------------------------------------------------------------------------
// Static device scratch
// ---------------------------------------------------------------------------
__device__ int   g_deg[NN];
__device__ float g_dinv[NN];
__device__ int   g_rowoff[NN + 1];
__device__ int   g_cursor[NN];
__device__ int   g_bsum[SCAN_B];
__device__ int   g_boff[SCAN_B];
__device__ int   g_csr_src[NE];

__device__ __nv_bfloat16 g_xa0[(size_t)NN * HID];
__device__ __nv_bfloat16 g_xa1[(size_t)NN * HID];
__device__ __nv_bfloat16 g_e0[(size_t)NN * EMB_W];
__device__ __nv_bfloat16 g_e1[(size_t)NN * EMB_W];
__device__ float         g_hA[(size_t)NN * HID];
__device__ float         g_hB[(size_t)NN * HID];
__device__ __nv_bfloat16 g_t1a[(size_t)NN * HID];
__device__ __nv_bfloat16 g_t1b[(size_t)NN * HID];
__device__ __nv_bfloat16 g_t2a[(size_t)NN * HID];
__device__ __nv_bfloat16 g_t2b[(size_t)NN * HID];
__device__ __nv_bfloat16 g_t3a[(size_t)NN * 256];
__device__ __nv_bfloat16 g_t3b[(size_t)NN * 256];
__device__ __nv_bfloat16 g_w0[344064];
__device__ __nv_bfloat16 g_w1[344064];

// ---------------------------------------------------------------------------
// Helpers
// ---------------------------------------------------------------------------
__device__ __forceinline__ uint32_t s2u(const void* p) {
    uint32_t a;
    asm("{ .reg .u64 t; cvta.to.shared.u64 t, %1; cvt.u32.u64 %0, t; }" : "=r"(a) : "l"(p));
    return a;
}

#define SWZ(o) ((o) ^ (((o) >> 3) & 0x70))

__device__ __forceinline__ void cp16(uint32_t s, const void* g, bool v) {
    int sz = v ? 16 : 0;
    asm volatile("cp.async.cg.shared.global [%0], [%1], 16, %2;"
                 :: "r"(s), "l"(g), "r"(sz) : "memory");
}
__device__ __forceinline__ void cp_commit() {
    asm volatile("cp.async.commit_group;" ::: "memory");
}
__device__ __forceinline__ void cp_wait1() {
    asm volatile("cp.async.wait_group 1;" ::: "memory");
}

__device__ __forceinline__ void ldsm_x4(uint32_t* r, uint32_t addr) {
    asm volatile("ldmatrix.sync.aligned.m8n8.x4.shared.b16 {%0,%1,%2,%3}, [%4];"
                 : "=r"(r[0]), "=r"(r[1]), "=r"(r[2]), "=r"(r[3]) : "r"(addr));
}

__device__ __forceinline__ void mma16816(float* d, const uint32_t* a, const uint32_t* b) {
    asm volatile(
        "mma.sync.aligned.m16n8k16.row.col.f32.bf16.bf16.f32 "
        "{%0,%1,%2,%3}, {%4,%5,%6,%7}, {%8,%9}, {%0,%1,%2,%3};"
        : "+f"(d[0]), "+f"(d[1]), "+f"(d[2]), "+f"(d[3])
        : "r"(a[0]), "r"(a[1]), "r"(a[2]), "r"(a[3]), "r"(b[0]), "r"(b[1]));
}

// ---------------------------------------------------------------------------
// CSR build
// ---------------------------------------------------------------------------
__global__ void k_zero_deg() {
    int i = blockIdx.x * blockDim.x + threadIdx.x;
    if (i < NN) g_deg[i] = 0;
}

__global__ void k_hist(const int* __restrict__ ei) {
    int e = blockIdx.x * blockDim.x + threadIdx.x;
    if (e < NE) atomicAdd(&g_deg[ei[NE + e]], 1);
}

__global__ void k_scan1() {
    __shared__ int sh[1024];
    int i = blockIdx.x * 1024 + threadIdx.x;
    int v = (i < NN) ? g_deg[i] : 0;
    sh[threadIdx.x] = v;
    __syncthreads();
    #pragma unroll
    for (int off = 1; off < 1024; off <<= 1) {
        int t = (threadIdx.x >= off) ? sh[threadIdx.x - off] : 0;
        __syncthreads();
        sh[threadIdx.x] += t;
        __syncthreads();
    }
    int incl = sh[threadIdx.x];
    if (i < NN) g_rowoff[i] = incl - v;
    if (threadIdx.x == 1023) g_bsum[blockIdx.x] = incl;
}

__global__ void k_scan2() {
    __shared__ int sh[128];
    int t = threadIdx.x;
    int v = (t < SCAN_B) ? g_bsum[t] : 0;
    sh[t] = v;
    __syncthreads();
    #pragma unroll
    for (int off = 1; off < 128; off <<= 1) {
        int u = (t >= off) ? sh[t - off] : 0;
        __syncthreads();
        sh[t] += u;
        __syncthreads();
    }
    if (t < SCAN_B) g_boff[t] = sh[t] - v;
}

__global__ void k_scan3() {
    int i = blockIdx.x * 1024 + threadIdx.x;
    if (i < NN) {
        int r = g_rowoff[i] + g_boff[blockIdx.x];
        g_rowoff[i] = r;
        g_cursor[i] = r;
        g_dinv[i]   = rsqrtf((float)(g_deg[i] + 1));
    }
    if (i == 0) g_rowoff[NN] = NE;
}

__global__ void k_scatter(const int* __restrict__ ei) {
    int e = blockIdx.x * blockDim.x + threadIdx.x;
    if (e < NE) {
        int src = ei[e];
        int dst = ei[NE + e];
        int pos = atomicAdd(&g_cursor[dst], 1);
        g_csr_src[pos] = src;
    }
}

// ---------------------------------------------------------------------------
// Conversions
// ---------------------------------------------------------------------------
__global__ void k_cvt_x(const float* __restrict__ x) {
    size_t i = (size_t)blockIdx.x * blockDim.x + threadIdx.x;
    if (i < (size_t)NN * HID) {
        float v = x[i];
        __nv_bfloat16 h = __float2bfloat16_rn(v);
        g_xa0[i] = h;
        g_xa1[i] = __float2bfloat16_rn(v - __bfloat162float(h));
    }
}

// All 9 weights: [K x N] fp32 -> transposed split bf16 [N x K], one kernel.
__global__ void k_prep_all(const float* __restrict__ s0, const float* __restrict__ s1,
                           const float* __restrict__ s2, const float* __restrict__ s3,
                           const float* __restrict__ s4, const float* __restrict__ s5,
                           const float* __restrict__ s6, const float* __restrict__ s7,
                           const float* __restrict__ s8)
{
    int b = blockIdx.x;
    const float* src; int K, N, base; size_t off;
    if      (b <   64) { src = s0; K = 128; N = 128; base =    0; off = 0; }
    else if (b <  128) { src = s1; K = 128; N = 128; base =   64; off = 16384; }
    else if (b <  256) { src = s2; K = 256; N = 128; base =  128; off = 32768; }
    else if (b <  448) { src = s3; K = 384; N = 128; base =  256; off = 65536; }
    else if (b <  704) { src = s4; K = 512; N = 128; base =  448; off = 114688; }
    else if (b < 1024) { src = s5; K = 640; N = 128; base =  704; off = 180224; }
    else if (b < 1088) { src = s6; K = 128; N = 128; base = 1024; off = 262144; }
    else if (b < 1216) { src = s7; K = 128; N = 256; base = 1088; off = 278528; }
    else               { src = s8; K = 256; N = 128; base = 1216; off = 311296; }

    int i = (b - base) * 256 + threadIdx.x;
    if (i < K * N) {
        int k = i / N, n = i % N;
        float v = src[i];
        __nv_bfloat16 h = __float2bfloat16_rn(v);
        g_w0[off + (size_t)n * K + k] = h;
        g_w1[off + (size_t)n * K + k] = __float2bfloat16_rn(v - __bfloat162float(h));
    }
}

// ---------------------------------------------------------------------------
// HMMA GEMM (R6 config): C[nrows x (128*gridDim.y)] = act(A @ B^T + Cacc + bias)
// BM=64, BN=128, BK=64, 256 threads / 8 warps (2x4 grid, 32x32 warp tiles),
// 2-stage cp.async pipeline, 96KB SMEM -> 2 CTAs/SM.
// B row stride = ldb (>= K; supports K-split weight slices).
// Cacc: optional fp32 accumulate input, stride ldcf.
// ---------------------------------------------------------------------------
#define ST_A0 0
#define ST_A1 8192
#define ST_B0 16384
#define ST_B1 32768
#define STAGE_BYTES 49152
#define GEMM_SMEM (2 * STAGE_BYTES)

__global__ __launch_bounds__(256, 2)
void k_mma_gemm(const __nv_bfloat16* __restrict__ A0,
                const __nv_bfloat16* __restrict__ A1, int lda, int K,
                const __nv_bfloat16* __restrict__ B0,
                const __nv_bfloat16* __restrict__ B1, int ldb,
                const float* __restrict__ bias,
                const float* __restrict__ Cacc,
                int act, int out_mode,
                float* __restrict__ Cf, int ldcf,
                __nv_bfloat16* __restrict__ C0,
                __nv_bfloat16* __restrict__ C1, int ldcb, int col_off,
                int nrows)
{
    extern __shared__ __align__(1024) char smem[];
    uint32_t sbase = s2u(smem);

    const int tid  = threadIdx.x;
    const int wid  = tid >> 5;
    const int lane = tid & 31;
    const int wm   = wid & 1;
    const int wn   = wid >> 1;
    const int rowBase = blockIdx.x * 64;
    const int nchunks = K >> 6;

    const __nv_bfloat16* B0p = B0 + (size_t)blockIdx.y * 128 * ldb;
    const __nv_bfloat16* B1p = B1 + (size_t)blockIdx.y * 128 * ldb;
    const float* biasp = bias ? bias + blockIdx.y * 128 : nullptr;
    const int colBase = col_off + blockIdx.y * 128;

    float acc[2][4][4];
    #pragma unroll
    for (int i = 0; i < 2; i++)
        #pragma unroll
        for (int j = 0; j < 4; j++)
            #pragma unroll
            for (int c = 0; c < 4; c++) acc[i][j][c] = 0.0f;

    auto load_stage = [&](int s, int kc) {
        uint32_t st = sbase + s * STAGE_BYTES;
        #pragma unroll
        for (int i = 0; i < 2; i++) {
            int idx = tid + i * 256;
            int r   = idx >> 3;
            int c16 = (idx & 7) * 16;
            uint32_t sw = SWZ((uint32_t)(r * 128 + c16));
            int  grow = rowBase + r;
            bool v = grow < nrows;
            int  crow = v ? grow : 0;
            size_t abo = ((size_t)crow * lda + (size_t)kc * 64) * 2 + c16;
            cp16(st + ST_A0 + sw, (const char*)A0 + abo, v);
            cp16(st + ST_A1 + sw, (const char*)A1 + abo, v);
        }
        #pragma unroll
        for (int i = 0; i < 4; i++) {
            int idx = tid + i * 256;
            int r   = idx >> 3;
            int c16 = (idx & 7) * 16;
            uint32_t sw = SWZ((uint32_t)(r * 128 + c16));
            size_t bbo = ((size_t)r * ldb + (size_t)kc * 64) * 2 + c16;
            cp16(st + ST_B0 + sw, (const char*)B0p + bbo, true);
            cp16(st + ST_B1 + sw, (const char*)B1p + bbo, true);
        }
    };

    load_stage(0, 0);
    cp_commit();

    const int nladd = (lane & 7) + ((lane >> 4) << 3);
    const int kladd = ((lane >> 3) & 1) * 16;
    const int arow  = lane & 15;
    const int akoff = (lane >> 4) * 16;

    for (int kc = 0; kc < nchunks; kc++) {
        if (kc + 1 < nchunks) load_stage((kc + 1) & 1, kc + 1);
        cp_commit();
        cp_wait1();
        __syncthreads();

        uint32_t st = sbase + (kc & 1) * STAGE_BYTES;
        #pragma unroll
        for (int ks = 0; ks < 4; ks++) {
            int kb = ks * 32;
            uint32_t a0f[2][4], a1f[2][4];
            #pragma unroll
            for (int mt = 0; mt < 2; mt++) {
                uint32_t off = SWZ((uint32_t)((wm * 32 + mt * 16 + arow) * 128 + kb + akoff));
                ldsm_x4(a0f[mt], st + ST_A0 + off);
                ldsm_x4(a1f[mt], st + ST_A1 + off);
            }
            uint32_t b0f[2][4], b1f[2][4];
            #pragma unroll
            for (int bt = 0; bt < 2; bt++) {
                uint32_t off = SWZ((uint32_t)((wn * 32 + bt * 16 + nladd) * 128 + kb + kladd));
                ldsm_x4(b0f[bt], st + ST_B0 + off);
                ldsm_x4(b1f[bt], st + ST_B1 + off);
            }
            #pragma unroll
            for (int mt = 0; mt < 2; mt++)
                #pragma unroll
                for (int nt = 0; nt < 4; nt++) {
                    const uint32_t* bp0 = &b0f[nt >> 1][(nt & 1) * 2];
                    const uint32_t* bp1 = &b1f[nt >> 1][(nt & 1) * 2];
                    mma16816(acc[mt][nt], a0f[mt], bp0);
                    mma16816(acc[mt][nt], a0f[mt], bp1);
                    mma16816(acc[mt][nt], a1f[mt], bp0);
                }
        }
        __syncthreads();
    }

    // Epilogue
    #pragma unroll
    for (int mt = 0; mt < 2; mt++) {
        #pragma unroll
        for (int nt = 0; nt < 4; nt++) {
            int row0 = rowBase + wm * 32 + mt * 16 + (lane >> 2);
            int col  = wn * 32 + nt * 8 + (lane & 3) * 2;
            #pragma unroll
            for (int half = 0; half < 2; half++) {
                int row = row0 + half * 8;
                if (row >= nrows) continue;
                float v0 = acc[mt][nt][half * 2 + 0];
                float v1 = acc[mt][nt][half * 2 + 1];
                if (Cacc) {
                    float2 a = *(const float2*)(Cacc + (size_t)row * ldcf + colBase + col);
                    v0 += a.x; v1 += a.y;
                }
                if (biasp) { v0 += biasp[col]; v1 += biasp[col + 1]; }
                if (act == 1) { v0 = fmaxf(v0, 0.f); v1 = fmaxf(v1, 0.f); }
                else if (act == 2) {
                    v0 = (v0 > 0.f) ? v0 : 0.1f * v0;
                    v1 = (v1 > 0.f) ? v1 : 0.1f * v1;
                }
                if (out_mode == 0) {
                    float2 o; o.x = v0; o.y = v1;
                    *(float2*)(Cf + (size_t)row * ldcf + colBase + col) = o;
                } else {
                    __nv_bfloat16 h0 = __float2bfloat16_rn(v0);
                    __nv_bfloat16 h1 = __float2bfloat16_rn(v1);
                    __nv_bfloat162 p; p.x = h0; p.y = h1;
                    *(__nv_bfloat162*)(C0 + (size_t)row * ldcb + colBase + col) = p;
                    __nv_bfloat162 q;
                    q.x = __float2bfloat16_rn(v0 - __bfloat162float(h0));
                    q.y = __float2bfloat16_rn(v1 - __bfloat162float(h1));
                    *(__nv_bfloat162*)(C1 + (size_t)row * ldcb + colBase + col) = q;
                }
            }
        }
    }
}

// ---------------------------------------------------------------------------
// GCN aggregation: warp per node, 4-edge unroll; bf16-split write into emb.
// ---------------------------------------------------------------------------
__global__ __launch_bounds__(256, 8)
void k_aggregate(const float* __restrict__ hbuf, const float* __restrict__ bias,
                 int col_off)
{
    int warp = threadIdx.x >> 5;
    int lane = threadIdx.x & 31;
    int node = blockIdx.x * 8 + warp;
    if (node >= NN) return;

    const float4* __restrict__ h4 = (const float4*)hbuf;

    int beg = g_rowoff[node];
    int end = g_rowoff[node + 1];
    float di = g_dinv[node];

    float4 acc = make_float4(0.f, 0.f, 0.f, 0.f);
    int j = beg;
    for (; j + 4 <= end; j += 4) {
        int s0 = g_csr_src[j];
        int s1 = g_csr_src[j + 1];
        int s2 = g_csr_src[j + 2];
        int s3 = g_csr_src[j + 3];
        float w0 = g_dinv[s0], w1 = g_dinv[s1], w2 = g_dinv[s2], w3 = g_dinv[s3];
        float4 v0 = h4[(size_t)s0 * 32 + lane];
        float4 v1 = h4[(size_t)s1 * 32 + lane];
        float4 v2 = h4[(size_t)s2 * 32 + lane];
        float4 v3 = h4[(size_t)s3 * 32 + lane];
        acc.x += w0 * v0.x + w1 * v1.x + w2 * v2.x + w3 * v3.x;
        acc.y += w0 * v0.y + w1 * v1.y + w2 * v2.y + w3 * v3.y;
        acc.z += w0 * v0.z + w1 * v1.z + w2 * v2.z + w3 * v3.z;
        acc.w += w0 * v0.w + w1 * v1.w + w2 * v2.w + w3 * v3.w;
    }
    for (; j < end; j++) {
        int s = g_csr_src[j];
        float w = g_dinv[s];
        float4 hv = h4[(size_t)s * 32 + lane];
        acc.x += w * hv.x; acc.y += w * hv.y;
        acc.z += w * hv.z; acc.w += w * hv.w;
    }
    float4 hs = h4[(size_t)node * 32 + lane];
    float dii = di * di;
    acc.x = di * acc.x + dii * hs.x;
    acc.y = di * acc.y + dii * hs.y;
    acc.z = di * acc.z + dii * hs.z;
    acc.w = di * acc.w + dii * hs.w;

    float4 b = ((const float4*)bias)[lane];
    float v[4];
    v[0] = fmaxf(acc.x + b.x, 0.f);
    v[1] = fmaxf(acc.y + b.y, 0.f);
    v[2] = fmaxf(acc.z + b.z, 0.f);
    v[3] = fmaxf(acc.w + b.w, 0.f);

    size_t base = (size_t)node * EMB_W + col_off + lane * 4;
    #pragma unroll
    for (int c = 0; c < 4; c += 2) {
        __nv_bfloat16 h0 = __float2bfloat16_rn(v[c]);
        __nv_bfloat16 h1 = __float2bfloat16_rn(v[c + 1]);
        __nv_bfloat162 p; p.x = h0; p.y = h1;
        *(__nv_bfloat162*)(g_e0 + base + c) = p;
        __nv_bfloat162 q;
        q.x = __float2bfloat16_rn(v[c]     - __bfloat162float(h0));
        q.y = __float2bfloat16_rn(v[c + 1] - __bfloat162float(h1));
        *(__nv_bfloat162*)(g_e1 + base + c) = q;
    }
}

// ---------------------------------------------------------------------------
// Launch
// ---------------------------------------------------------------------------
extern "C" void kernel_launch(void* const* d_in, const int* in_sizes, int n_in,
                              void* d_out, int out_size)
{
    const float* x   = (const float*)d_in[0];
    const int*   ei  = (const int*)  d_in[1];
    const float* pre_w = (const float*)d_in[2];
    const float* pre_b = (const float*)d_in[3];
    const float* conv_w[4] = { (const float*)d_in[4], (const float*)d_in[6],
                               (const float*)d_in[8], (const float*)d_in[10] };
    const float* conv_b[4] = { (const float*)d_in[5], (const float*)d_in[7],
                               (const float*)d_in[9], (const float*)d_in[11] };
    const float* pw1 = (const float*)d_in[12]; const float* pb1 = (const float*)d_in[13];
    const float* pw2 = (const float*)d_in[14]; const float* pb2 = (const float*)d_in[15];
    const float* pw3 = (const float*)d_in[16]; const float* pb3 = (const float*)d_in[17];
    const float* pw4 = (const float*)d_in[18]; const float* pb4 = (const float*)d_in[19];
    float* out = (float*)d_out;

    __nv_bfloat16 *xa0, *xa1, *e0, *e1, *t1a, *t1b, *t2a, *t2b, *t3a, *t3b, *w0, *w1;
    float *hA, *hB;
    cudaGetSymbolAddress((void**)&xa0, g_xa0);
    cudaGetSymbolAddress((void**)&xa1, g_xa1);
    cudaGetSymbolAddress((void**)&e0,  g_e0);
    cudaGetSymbolAddress((void**)&e1,  g_e1);
    cudaGetSymbolAddress((void**)&hA,  g_hA);
    cudaGetSymbolAddress((void**)&hB,  g_hB);
    cudaGetSymbolAddress((void**)&t1a, g_t1a);
    cudaGetSymbolAddress((void**)&t1b, g_t1b);
    cudaGetSymbolAddress((void**)&t2a, g_t2a);
    cudaGetSymbolAddress((void**)&t2b, g_t2b);
    cudaGetSymbolAddress((void**)&t3a, g_t3a);
    cudaGetSymbolAddress((void**)&t3b, g_t3b);
    cudaGetSymbolAddress((void**)&w0,  g_w0);
    cudaGetSymbolAddress((void**)&w1,  g_w1);

    cudaFuncSetAttribute(k_mma_gemm, cudaFuncAttributeMaxDynamicSharedMemorySize, GEMM_SMEM);

    // One-time stream/event creation (outside capture on first call).
    static cudaStream_t s_side = nullptr;
    static cudaEvent_t  s_fork = nullptr;
    static cudaEvent_t  s_evh[4] = {};   // h ready for agg l (recorded on main)
    static cudaEvent_t  s_eva[4] = {};   // agg l done (recorded on side)
    if (s_side == nullptr) {
        cudaStreamCreateWithFlags(&s_side, cudaStreamNonBlocking);
        cudaEventCreateWithFlags(&s_fork, cudaEventDisableTiming);
        for (int i = 0; i < 4; i++) {
            cudaEventCreateWithFlags(&s_evh[i], cudaEventDisableTiming);
            cudaEventCreateWithFlags(&s_eva[i], cudaEventDisableTiming);
        }
    }

    const int TB = 256;
    const int nodeBlocks = (NN + TB - 1) / TB;
    const int edgeBlocks = (NE + TB - 1) / TB;
    const size_t woff[9] = { 0, 16384, 32768, 65536, 114688, 180224, 262144, 278528, 311296 };
    const int aggBlocks = (NN + 7) / 8;

    float* hbuf[4] = { hA, hB, hA, hB };   // h buffer for conv layer l

    // ---- Fork: CSR build on side stream (record precedes wait in host order) ----
    cudaEventRecord(s_fork, 0);
    cudaStreamWaitEvent(s_side, s_fork, 0);
    k_zero_deg<<<nodeBlocks, TB, 0, s_side>>>();
    k_hist<<<edgeBlocks, TB, 0, s_side>>>(ei);
    k_scan1<<<SCAN_B, 1024, 0, s_side>>>();
    k_scan2<<<1, 128, 0, s_side>>>();
    k_scan3<<<SCAN_B, 1024, 0, s_side>>>();
    k_scatter<<<edgeBlocks, TB, 0, s_side>>>(ei);

    // ---- Main stream: prep, cvt, pre_mp, conv1 transform ----
    k_prep_all<<<1344, 256>>>(pre_w, conv_w[0], conv_w[1], conv_w[2], conv_w[3],
                              pw1, pw2, pw3, pw4);
    k_cvt_x<<<((size_t)NN * HID + 255) / 256, 256>>>(x);

    k_mma_gemm<<<GRID_M, 256, GEMM_SMEM>>>(xa0, xa1, HID, HID,
                                           w0 + woff[0], w1 + woff[0], HID,
                                           pre_b, nullptr, 0, 1, nullptr, 0,
                                           e0, e1, EMB_W, 0, NN);
    k_mma_gemm<<<GRID_M, 256, GEMM_SMEM>>>(e0, e1, EMB_W, HID,
                                           w0 + woff[1], w1 + woff[1], HID,
                                           nullptr, nullptr, 0, 0, hA, HID,
                                           nullptr, nullptr, 0, 0, NN);
    cudaEventRecord(s_evh[0], 0);

    // ---- Interleaved: agg l on side overlaps partial GEMM l+1 on main ----
    for (int l = 1; l < 4; l++) {
        // side: aggregate layer l-1 (event s_evh[l-1] already recorded)
        cudaStreamWaitEvent(s_side, s_evh[l - 1], 0);
        k_aggregate<<<aggBlocks, 256, 0, s_side>>>(hbuf[l - 1], conv_b[l - 1], HID * l);
        cudaEventRecord(s_eva[l - 1], s_side);

        int Kfull = HID * (l + 1);
        int Kold  = Kfull - HID;
        float* hn = hbuf[l];
        // main: partial GEMM over old columns (overlaps the aggregate above)
        k_mma_gemm<<<GRID_M, 256, GEMM_SMEM>>>(e0, e1, EMB_W, Kold,
                                               w0 + woff[1 + l], w1 + woff[1 + l], Kfull,
                                               nullptr, nullptr, 0, 0, hn, HID,
                                               nullptr, nullptr, 0, 0, NN);
        // main: final GEMM over fresh 128 columns (needs agg l-1)
        cudaStreamWaitEvent(0, s_eva[l - 1], 0);
        k_mma_gemm<<<GRID_M, 256, GEMM_SMEM>>>(e0 + Kold, e1 + Kold, EMB_W, HID,
                                               w0 + woff[1 + l] + Kold,
                                               w1 + woff[1 + l] + Kold, Kfull,
                                               nullptr, hn, 0, 0, hn, HID,
                                               nullptr, nullptr, 0, 0, NN);
        cudaEventRecord(s_evh[l], 0);
    }

    // side: aggregate layer 4
    cudaStreamWaitEvent(s_side, s_evh[3], 0);
    k_aggregate<<<aggBlocks, 256, 0, s_side>>>(hbuf[3], conv_b[3], HID * 4);
    cudaEventRecord(s_eva[3], s_side);

    // main: post1 partial (K=512, overlaps agg4) + final 128
    k_mma_gemm<<<GRID_M, 256, GEMM_SMEM>>>(e0, e1, EMB_W, 512,
                                           w0 + woff[5], w1 + woff[5], EMB_W,
                                           nullptr, nullptr, 0, 0, hA, HID,
                                           nullptr, nullptr, 0, 0, NN);
    cudaStreamWaitEvent(0, s_eva[3], 0);
    k_mma_gemm<<<GRID_M, 256, GEMM_SMEM>>>(e0 + 512, e1 + 512, EMB_W, HID,
                                           w0 + woff[5] + 512, w1 + woff[5] + 512, EMB_W,
                                           pb1, hA, 2, 1, nullptr, HID,
                                           t1a, t1b, HID, 0, NN);

    // post2, post3 (fused 2 N-blocks), post4
    k_mma_gemm<<<GRID_M, 256, GEMM_SMEM>>>(t1a, t1b, HID, HID,
                                           w0 + woff[6], w1 + woff[6], HID,
                                           pb2, nullptr, 1, 1, nullptr, 0,
                                           t2a, t2b, HID, 0, NN);
    k_mma_gemm<<<dim3(GRID_M, 2), 256, GEMM_SMEM>>>(t2a, t2b, HID, HID,
                                                    w0 + woff[7], w1 + woff[7], HID,
                                                    pb3, nullptr, 1, 1, nullptr, 0,
                                                    t3a, t3b, 256, 0, NN);
    k_mma_gemm<<<GRID_M, 256, GEMM_SMEM>>>(t3a, t3b, 256, 256,
                                           w0 + woff[8], w1 + woff[8], 256,
                                           pb4, nullptr, 0, 0, out, HID,
                                           nullptr, nullptr, 0, 0, NN);
}

// round 11
// speedup vs baseline: 1.1269x; 1.1269x over previous
#include <cuda_runtime.h>
#include <cuda_bf16.h>
#include <cstdint>

#define NN 100000
#define NE 1600000
#define HID 128
#define EMB_W 640
#define SCAN_B 98
#define GRID_M 1563           // ceil(NN/64)

// ---------------------------------------------------------------------------
// Static device scratch
// ---------------------------------------------------------------------------
__device__ int   g_deg[NN];
__device__ float g_dinv[NN];
__device__ int   g_rowoff[NN + 1];
__device__ int   g_cursor[NN];
__device__ int   g_bsum[SCAN_B];
__device__ int   g_boff[SCAN_B];
__device__ int   g_csr_src[NE];

__device__ __nv_bfloat16 g_xa0[(size_t)NN * HID];
__device__ __nv_bfloat16 g_xa1[(size_t)NN * HID];
__device__ __nv_bfloat16 g_e0[(size_t)NN * EMB_W];
__device__ __nv_bfloat16 g_e1[(size_t)NN * EMB_W];
__device__ float         g_h[(size_t)NN * HID];
__device__ __nv_bfloat16 g_t1a[(size_t)NN * HID];
__device__ __nv_bfloat16 g_t1b[(size_t)NN * HID];
__device__ __nv_bfloat16 g_t2a[(size_t)NN * HID];
__device__ __nv_bfloat16 g_t2b[(size_t)NN * HID];
__device__ __nv_bfloat16 g_t3a[(size_t)NN * 256];
__device__ __nv_bfloat16 g_t3b[(size_t)NN * 256];
__device__ __nv_bfloat16 g_w0[344064];
__device__ __nv_bfloat16 g_w1[344064];

// ---------------------------------------------------------------------------
// Helpers
// ---------------------------------------------------------------------------
__device__ __forceinline__ uint32_t s2u(const void* p) {
    uint32_t a;
    asm("{ .reg .u64 t; cvta.to.shared.u64 t, %1; cvt.u32.u64 %0, t; }" : "=r"(a) : "l"(p));
    return a;
}

#define SWZ(o) ((o) ^ (((o) >> 3) & 0x70))

__device__ __forceinline__ void cp16(uint32_t s, const void* g, bool v) {
    int sz = v ? 16 : 0;
    asm volatile("cp.async.cg.shared.global [%0], [%1], 16, %2;"
                 :: "r"(s), "l"(g), "r"(sz) : "memory");
}
__device__ __forceinline__ void cp_commit() {
    asm volatile("cp.async.commit_group;" ::: "memory");
}
__device__ __forceinline__ void cp_wait1() {
    asm volatile("cp.async.wait_group 1;" ::: "memory");
}

__device__ __forceinline__ void ldsm_x4(uint32_t* r, uint32_t addr) {
    asm volatile("ldmatrix.sync.aligned.m8n8.x4.shared.b16 {%0,%1,%2,%3}, [%4];"
                 : "=r"(r[0]), "=r"(r[1]), "=r"(r[2]), "=r"(r[3]) : "r"(addr));
}

__device__ __forceinline__ void mma16816(float* d, const uint32_t* a, const uint32_t* b) {
    asm volatile(
        "mma.sync.aligned.m16n8k16.row.col.f32.bf16.bf16.f32 "
        "{%0,%1,%2,%3}, {%4,%5,%6,%7}, {%8,%9}, {%0,%1,%2,%3};"
        : "+f"(d[0]), "+f"(d[1]), "+f"(d[2]), "+f"(d[3])
        : "r"(a[0]), "r"(a[1]), "r"(a[2]), "r"(a[3]), "r"(b[0]), "r"(b[1]));
}

// ---------------------------------------------------------------------------
// CSR build
// ---------------------------------------------------------------------------
__global__ void k_zero_deg() {
    int i = blockIdx.x * blockDim.x + threadIdx.x;
    if (i < NN) g_deg[i] = 0;
}

__global__ void k_hist(const int* __restrict__ ei) {
    int e = blockIdx.x * blockDim.x + threadIdx.x;
    if (e < NE) atomicAdd(&g_deg[ei[NE + e]], 1);
}

__global__ void k_scan1() {
    __shared__ int sh[1024];
    int i = blockIdx.x * 1024 + threadIdx.x;
    int v = (i < NN) ? g_deg[i] : 0;
    sh[threadIdx.x] = v;
    __syncthreads();
    #pragma unroll
    for (int off = 1; off < 1024; off <<= 1) {
        int t = (threadIdx.x >= off) ? sh[threadIdx.x - off] : 0;
        __syncthreads();
        sh[threadIdx.x] += t;
        __syncthreads();
    }
    int incl = sh[threadIdx.x];
    if (i < NN) g_rowoff[i] = incl - v;
    if (threadIdx.x == 1023) g_bsum[blockIdx.x] = incl;
}

__global__ void k_scan2() {
    __shared__ int sh[128];
    int t = threadIdx.x;
    int v = (t < SCAN_B) ? g_bsum[t] : 0;
    sh[t] = v;
    __syncthreads();
    #pragma unroll
    for (int off = 1; off < 128; off <<= 1) {
        int u = (t >= off) ? sh[t - off] : 0;
        __syncthreads();
        sh[t] += u;
        __syncthreads();
    }
    if (t < SCAN_B) g_boff[t] = sh[t] - v;
}

__global__ void k_scan3() {
    int i = blockIdx.x * 1024 + threadIdx.x;
    if (i < NN) {
        int r = g_rowoff[i] + g_boff[blockIdx.x];
        g_rowoff[i] = r;
        g_cursor[i] = r;
        g_dinv[i]   = rsqrtf((float)(g_deg[i] + 1));
    }
    if (i == 0) g_rowoff[NN] = NE;
}

__global__ void k_scatter(const int* __restrict__ ei) {
    int e = blockIdx.x * blockDim.x + threadIdx.x;
    if (e < NE) {
        int src = ei[e];
        int dst = ei[NE + e];
        int pos = atomicAdd(&g_cursor[dst], 1);
        g_csr_src[pos] = src;
    }
}

// ---------------------------------------------------------------------------
// Conversions
// ---------------------------------------------------------------------------
__global__ void k_cvt_x(const float* __restrict__ x) {
    size_t i = (size_t)blockIdx.x * blockDim.x + threadIdx.x;
    if (i < (size_t)NN * HID) {
        float v = x[i];
        __nv_bfloat16 h = __float2bfloat16_rn(v);
        g_xa0[i] = h;
        g_xa1[i] = __float2bfloat16_rn(v - __bfloat162float(h));
    }
}

// All 9 weights: [K x N] fp32 -> transposed split bf16 [N x K], one kernel.
__global__ void k_prep_all(const float* __restrict__ s0, const float* __restrict__ s1,
                           const float* __restrict__ s2, const float* __restrict__ s3,
                           const float* __restrict__ s4, const float* __restrict__ s5,
                           const float* __restrict__ s6, const float* __restrict__ s7,
                           const float* __restrict__ s8)
{
    int b = blockIdx.x;
    const float* src; int K, N, base; size_t off;
    if      (b <   64) { src = s0; K = 128; N = 128; base =    0; off = 0; }
    else if (b <  128) { src = s1; K = 128; N = 128; base =   64; off = 16384; }
    else if (b <  256) { src = s2; K = 256; N = 128; base =  128; off = 32768; }
    else if (b <  448) { src = s3; K = 384; N = 128; base =  256; off = 65536; }
    else if (b <  704) { src = s4; K = 512; N = 128; base =  448; off = 114688; }
    else if (b < 1024) { src = s5; K = 640; N = 128; base =  704; off = 180224; }
    else if (b < 1088) { src = s6; K = 128; N = 128; base = 1024; off = 262144; }
    else if (b < 1216) { src = s7; K = 128; N = 256; base = 1088; off = 278528; }
    else               { src = s8; K = 256; N = 128; base = 1216; off = 311296; }

    int i = (b - base) * 256 + threadIdx.x;
    if (i < K * N) {
        int k = i / N, n = i % N;
        float v = src[i];
        __nv_bfloat16 h = __float2bfloat16_rn(v);
        g_w0[off + (size_t)n * K + k] = h;
        g_w1[off + (size_t)n * K + k] = __float2bfloat16_rn(v - __bfloat162float(h));
    }
}

// ---------------------------------------------------------------------------
// HMMA GEMM (R6 config + ks-level fragment double-buffering):
// C[nrows x (128*gridDim.y)] = act(A @ B^T + bias)
// BM=64, BN=128, BK=64, 256 threads / 8 warps (2x4 grid, 32x32 warp tiles),
// 2-stage cp.async pipeline, 96KB SMEM -> 2 CTAs/SM.
// ---------------------------------------------------------------------------
#define ST_A0 0
#define ST_A1 8192
#define ST_B0 16384
#define ST_B1 32768
#define STAGE_BYTES 49152
#define GEMM_SMEM (2 * STAGE_BYTES)

__global__ __launch_bounds__(256, 2)
void k_mma_gemm(const __nv_bfloat16* __restrict__ A0,
                const __nv_bfloat16* __restrict__ A1, int lda, int K,
                const __nv_bfloat16* __restrict__ B0,
                const __nv_bfloat16* __restrict__ B1,
                const float* __restrict__ bias, int act, int out_mode,
                float* __restrict__ Cf, int ldcf,
                __nv_bfloat16* __restrict__ C0,
                __nv_bfloat16* __restrict__ C1, int ldcb, int col_off,
                int nrows)
{
    extern __shared__ __align__(1024) char smem[];
    uint32_t sbase = s2u(smem);

    const int tid  = threadIdx.x;
    const int wid  = tid >> 5;
    const int lane = tid & 31;
    const int wm   = wid & 1;          // row block: 32*wm (within 64)
    const int wn   = wid >> 1;         // col block: 32*wn (0..3)
    const int rowBase = blockIdx.x * 64;
    const int nchunks = K >> 6;

    // N-block select (for fused wide-N launches)
    const __nv_bfloat16* B0p = B0 + (size_t)blockIdx.y * 128 * K;
    const __nv_bfloat16* B1p = B1 + (size_t)blockIdx.y * 128 * K;
    const float* biasp = bias ? bias + blockIdx.y * 128 : nullptr;
    const int colBase = col_off + blockIdx.y * 128;

    float acc[2][4][4];
    #pragma unroll
    for (int i = 0; i < 2; i++)
        #pragma unroll
        for (int j = 0; j < 4; j++)
            #pragma unroll
            for (int c = 0; c < 4; c++) acc[i][j][c] = 0.0f;

    auto load_stage = [&](int s, int kc) {
        uint32_t st = sbase + s * STAGE_BYTES;
        // A tiles: 64 rows x 64 bf16 (128B rows) for hi and lo
        #pragma unroll
        for (int i = 0; i < 2; i++) {
            int idx = tid + i * 256;          // 0..511
            int r   = idx >> 3;               // 0..63
            int c16 = (idx & 7) * 16;
            uint32_t sw = SWZ((uint32_t)(r * 128 + c16));
            int  grow = rowBase + r;
            bool v = grow < nrows;
            int  crow = v ? grow : 0;
            size_t abo = ((size_t)crow * lda + (size_t)kc * 64) * 2 + c16;
            cp16(st + ST_A0 + sw, (const char*)A0 + abo, v);
            cp16(st + ST_A1 + sw, (const char*)A1 + abo, v);
        }
        // B tiles: 128 rows x 64 bf16 for hi and lo
        #pragma unroll
        for (int i = 0; i < 4; i++) {
            int idx = tid + i * 256;          // 0..1023
            int r   = idx >> 3;               // 0..127
            int c16 = (idx & 7) * 16;
            uint32_t sw = SWZ((uint32_t)(r * 128 + c16));
            size_t bbo = ((size_t)r * K + (size_t)kc * 64) * 2 + c16;
            cp16(st + ST_B0 + sw, (const char*)B0p + bbo, true);
            cp16(st + ST_B1 + sw, (const char*)B1p + bbo, true);
        }
    };

    load_stage(0, 0);
    cp_commit();

    const int nladd = (lane & 7) + ((lane >> 4) << 3);  // B ldmatrix n offset
    const int kladd = ((lane >> 3) & 1) * 16;           // B ldmatrix k byte offset
    const int arow  = lane & 15;                        // A ldmatrix row offset
    const int akoff = (lane >> 4) * 16;                 // A ldmatrix k byte offset

    // Double-buffered operand fragments across ks-steps
    uint32_t a0f[2][2][4], a1f[2][2][4];   // [buf][mt][r]
    uint32_t b0f[2][2][4], b1f[2][2][4];   // [buf][bt][r]

    for (int kc = 0; kc < nchunks; kc++) {
        if (kc + 1 < nchunks) load_stage((kc + 1) & 1, kc + 1);
        cp_commit();
        cp_wait1();
        __syncthreads();

        uint32_t st = sbase + (kc & 1) * STAGE_BYTES;

        // prime ks=0 fragments
        {
            #pragma unroll
            for (int mt = 0; mt < 2; mt++) {
                uint32_t off = SWZ((uint32_t)((wm * 32 + mt * 16 + arow) * 128 + akoff));
                ldsm_x4(a0f[0][mt], st + ST_A0 + off);
                ldsm_x4(a1f[0][mt], st + ST_A1 + off);
            }
            #pragma unroll
            for (int bt = 0; bt < 2; bt++) {
                uint32_t off = SWZ((uint32_t)((wn * 32 + bt * 16 + nladd) * 128 + kladd));
                ldsm_x4(b0f[0][bt], st + ST_B0 + off);
                ldsm_x4(b1f[0][bt], st + ST_B1 + off);
            }
        }

        #pragma unroll
        for (int ks = 0; ks < 4; ks++) {
            // prefetch ks+1 fragments into the other buffer
            if (ks < 3) {
                int kb = (ks + 1) * 32;
                int nb = (ks + 1) & 1;
                #pragma unroll
                for (int mt = 0; mt < 2; mt++) {
                    uint32_t off = SWZ((uint32_t)((wm * 32 + mt * 16 + arow) * 128 + kb + akoff));
                    ldsm_x4(a0f[nb][mt], st + ST_A0 + off);
                    ldsm_x4(a1f[nb][mt], st + ST_A1 + off);
                }
                #pragma unroll
                for (int bt = 0; bt < 2; bt++) {
                    uint32_t off = SWZ((uint32_t)((wn * 32 + bt * 16 + nladd) * 128 + kb + kladd));
                    ldsm_x4(b0f[nb][bt], st + ST_B0 + off);
                    ldsm_x4(b1f[nb][bt], st + ST_B1 + off);
                }
            }
            // compute with current buffer
            int cb = ks & 1;
            #pragma unroll
            for (int mt = 0; mt < 2; mt++)
                #pragma unroll
                for (int nt = 0; nt < 4; nt++) {
                    const uint32_t* bp0 = &b0f[cb][nt >> 1][(nt & 1) * 2];
                    const uint32_t* bp1 = &b1f[cb][nt >> 1][(nt & 1) * 2];
                    mma16816(acc[mt][nt], a0f[cb][mt], bp0);   // a_hi * b_hi
                    mma16816(acc[mt][nt], a0f[cb][mt], bp1);   // a_hi * b_lo
                    mma16816(acc[mt][nt], a1f[cb][mt], bp0);   // a_lo * b_hi
                }
        }
        __syncthreads();
    }

    // Epilogue: warp tile rows wm*32 + mt*16, cols wn*32 + nt*8
    #pragma unroll
    for (int mt = 0; mt < 2; mt++) {
        #pragma unroll
        for (int nt = 0; nt < 4; nt++) {
            int row0 = rowBase + wm * 32 + mt * 16 + (lane >> 2);
            int col  = wn * 32 + nt * 8 + (lane & 3) * 2;
            #pragma unroll
            for (int half = 0; half < 2; half++) {
                int row = row0 + half * 8;
                if (row >= nrows) continue;
                float v0 = acc[mt][nt][half * 2 + 0];
                float v1 = acc[mt][nt][half * 2 + 1];
                if (biasp) { v0 += biasp[col]; v1 += biasp[col + 1]; }
                if (act == 1) { v0 = fmaxf(v0, 0.f); v1 = fmaxf(v1, 0.f); }
                else if (act == 2) {
                    v0 = (v0 > 0.f) ? v0 : 0.1f * v0;
                    v1 = (v1 > 0.f) ? v1 : 0.1f * v1;
                }
                if (out_mode == 0) {
                    float2 o; o.x = v0; o.y = v1;
                    *(float2*)(Cf + (size_t)row * ldcf + colBase + col) = o;
                } else {
                    __nv_bfloat16 h0 = __float2bfloat16_rn(v0);
                    __nv_bfloat16 h1 = __float2bfloat16_rn(v1);
                    __nv_bfloat162 p; p.x = h0; p.y = h1;
                    *(__nv_bfloat162*)(C0 + (size_t)row * ldcb + colBase + col) = p;
                    __nv_bfloat162 q;
                    q.x = __float2bfloat16_rn(v0 - __bfloat162float(h0));
                    q.y = __float2bfloat16_rn(v1 - __bfloat162float(h1));
                    *(__nv_bfloat162*)(C1 + (size_t)row * ldcb + colBase + col) = q;
                }
            }
        }
    }
}

// ---------------------------------------------------------------------------
// GCN aggregation: warp per node, 4-edge unroll; bf16-split write into emb
// ---------------------------------------------------------------------------
__global__ __launch_bounds__(256, 8)
void k_aggregate(const float* __restrict__ bias, int col_off)
{
    int warp = threadIdx.x >> 5;
    int lane = threadIdx.x & 31;
    int node = blockIdx.x * 8 + warp;
    if (node >= NN) return;

    const float4* __restrict__ h4 = (const float4*)g_h;

    int beg = g_rowoff[node];
    int end = g_rowoff[node + 1];
    float di = g_dinv[node];

    float4 acc = make_float4(0.f, 0.f, 0.f, 0.f);
    int j = beg;
    for (; j + 4 <= end; j += 4) {
        int s0 = g_csr_src[j];
        int s1 = g_csr_src[j + 1];
        int s2 = g_csr_src[j + 2];
        int s3 = g_csr_src[j + 3];
        float w0 = g_dinv[s0], w1 = g_dinv[s1], w2 = g_dinv[s2], w3 = g_dinv[s3];
        float4 v0 = h4[(size_t)s0 * 32 + lane];
        float4 v1 = h4[(size_t)s1 * 32 + lane];
        float4 v2 = h4[(size_t)s2 * 32 + lane];
        float4 v3 = h4[(size_t)s3 * 32 + lane];
        acc.x += w0 * v0.x + w1 * v1.x + w2 * v2.x + w3 * v3.x;
        acc.y += w0 * v0.y + w1 * v1.y + w2 * v2.y + w3 * v3.y;
        acc.z += w0 * v0.z + w1 * v1.z + w2 * v2.z + w3 * v3.z;
        acc.w += w0 * v0.w + w1 * v1.w + w2 * v2.w + w3 * v3.w;
    }
    for (; j < end; j++) {
        int s = g_csr_src[j];
        float w = g_dinv[s];
        float4 hv = h4[(size_t)s * 32 + lane];
        acc.x += w * hv.x; acc.y += w * hv.y;
        acc.z += w * hv.z; acc.w += w * hv.w;
    }
    float4 hs = h4[(size_t)node * 32 + lane];
    float dii = di * di;
    acc.x = di * acc.x + dii * hs.x;
    acc.y = di * acc.y + dii * hs.y;
    acc.z = di * acc.z + dii * hs.z;
    acc.w = di * acc.w + dii * hs.w;

    float4 b = ((const float4*)bias)[lane];
    float v[4];
    v[0] = fmaxf(acc.x + b.x, 0.f);
    v[1] = fmaxf(acc.y + b.y, 0.f);
    v[2] = fmaxf(acc.z + b.z, 0.f);
    v[3] = fmaxf(acc.w + b.w, 0.f);

    size_t base = (size_t)node * EMB_W + col_off + lane * 4;
    #pragma unroll
    for (int c = 0; c < 4; c += 2) {
        __nv_bfloat16 h0 = __float2bfloat16_rn(v[c]);
        __nv_bfloat16 h1 = __float2bfloat16_rn(v[c + 1]);
        __nv_bfloat162 p; p.x = h0; p.y = h1;
        *(__nv_bfloat162*)(g_e0 + base + c) = p;
        __nv_bfloat162 q;
        q.x = __float2bfloat16_rn(v[c]     - __bfloat162float(h0));
        q.y = __float2bfloat16_rn(v[c + 1] - __bfloat162float(h1));
        *(__nv_bfloat162*)(g_e1 + base + c) = q;
    }
}

// ---------------------------------------------------------------------------
// Launch (R8 structure: CSR on side stream, aggs serial on main)
// ---------------------------------------------------------------------------
extern "C" void kernel_launch(void* const* d_in, const int* in_sizes, int n_in,
                              void* d_out, int out_size)
{
    const float* x   = (const float*)d_in[0];
    const int*   ei  = (const int*)  d_in[1];
    const float* pre_w = (const float*)d_in[2];
    const float* pre_b = (const float*)d_in[3];
    const float* conv_w[4] = { (const float*)d_in[4], (const float*)d_in[6],
                               (const float*)d_in[8], (const float*)d_in[10] };
    const float* conv_b[4] = { (const float*)d_in[5], (const float*)d_in[7],
                               (const float*)d_in[9], (const float*)d_in[11] };
    const float* pw1 = (const float*)d_in[12]; const float* pb1 = (const float*)d_in[13];
    const float* pw2 = (const float*)d_in[14]; const float* pb2 = (const float*)d_in[15];
    const float* pw3 = (const float*)d_in[16]; const float* pb3 = (const float*)d_in[17];
    const float* pw4 = (const float*)d_in[18]; const float* pb4 = (const float*)d_in[19];
    float* out = (float*)d_out;

    __nv_bfloat16 *xa0, *xa1, *e0, *e1, *t1a, *t1b, *t2a, *t2b, *t3a, *t3b, *w0, *w1;
    float* hp;
    cudaGetSymbolAddress((void**)&xa0, g_xa0);
    cudaGetSymbolAddress((void**)&xa1, g_xa1);
    cudaGetSymbolAddress((void**)&e0,  g_e0);
    cudaGetSymbolAddress((void**)&e1,  g_e1);
    cudaGetSymbolAddress((void**)&t1a, g_t1a);
    cudaGetSymbolAddress((void**)&t1b, g_t1b);
    cudaGetSymbolAddress((void**)&t2a, g_t2a);
    cudaGetSymbolAddress((void**)&t2b, g_t2b);
    cudaGetSymbolAddress((void**)&t3a, g_t3a);
    cudaGetSymbolAddress((void**)&t3b, g_t3b);
    cudaGetSymbolAddress((void**)&w0,  g_w0);
    cudaGetSymbolAddress((void**)&w1,  g_w1);
    cudaGetSymbolAddress((void**)&hp,  g_h);

    cudaFuncSetAttribute(k_mma_gemm, cudaFuncAttributeMaxDynamicSharedMemorySize, GEMM_SMEM);

    // One-time stream/event creation (outside capture on first call).
    static cudaStream_t s_side = nullptr;
    static cudaEvent_t  s_ev1 = nullptr, s_ev2 = nullptr;
    if (s_side == nullptr) {
        cudaStreamCreateWithFlags(&s_side, cudaStreamNonBlocking);
        cudaEventCreateWithFlags(&s_ev1, cudaEventDisableTiming);
        cudaEventCreateWithFlags(&s_ev2, cudaEventDisableTiming);
    }

    const int TB = 256;
    const int nodeBlocks = (NN + TB - 1) / TB;
    const int edgeBlocks = (NE + TB - 1) / TB;
    const size_t woff[9] = { 0, 16384, 32768, 65536, 114688, 180224, 262144, 278528, 311296 };

    // Fork: CSR build on side stream, concurrent with weight prep + early GEMMs.
    cudaEventRecord(s_ev1, 0);
    cudaStreamWaitEvent(s_side, s_ev1, 0);
    k_zero_deg<<<nodeBlocks, TB, 0, s_side>>>();
    k_hist<<<edgeBlocks, TB, 0, s_side>>>(ei);
    k_scan1<<<SCAN_B, 1024, 0, s_side>>>();
    k_scan2<<<1, 128, 0, s_side>>>();
    k_scan3<<<SCAN_B, 1024, 0, s_side>>>();
    k_scatter<<<edgeBlocks, TB, 0, s_side>>>(ei);
    cudaEventRecord(s_ev2, s_side);

    // Main stream: weight prep, cvt, pre GEMM, conv1 GEMM
    k_prep_all<<<1344, 256>>>(pre_w, conv_w[0], conv_w[1], conv_w[2], conv_w[3],
                              pw1, pw2, pw3, pw4);
    k_cvt_x<<<((size_t)NN * HID + 255) / 256, 256>>>(x);

    k_mma_gemm<<<GRID_M, 256, GEMM_SMEM>>>(xa0, xa1, HID, HID, w0 + woff[0], w1 + woff[0],
                                           pre_b, 0, 1, nullptr, 0, e0, e1, EMB_W, 0, NN);
    k_mma_gemm<<<GRID_M, 256, GEMM_SMEM>>>(e0, e1, EMB_W, HID, w0 + woff[1], w1 + woff[1],
                                           nullptr, 0, 0, hp, HID,
                                           nullptr, nullptr, 0, 0, NN);

    // Join: aggregation needs CSR
    cudaStreamWaitEvent(0, s_ev2, 0);
    k_aggregate<<<(NN + 7) / 8, 256>>>(conv_b[0], HID);

    // Layers 2-4
    for (int l = 1; l < 4; l++) {
        int K = HID * (l + 1);
        k_mma_gemm<<<GRID_M, 256, GEMM_SMEM>>>(e0, e1, EMB_W, K,
                                               w0 + woff[1 + l], w1 + woff[1 + l],
                                               nullptr, 0, 0, hp, HID,
                                               nullptr, nullptr, 0, 0, NN);
        k_aggregate<<<(NN + 7) / 8, 256>>>(conv_b[l], K);
    }

    // post_mp
    k_mma_gemm<<<GRID_M, 256, GEMM_SMEM>>>(e0, e1, EMB_W, EMB_W, w0 + woff[5], w1 + woff[5],
                                           pb1, 2, 1, nullptr, 0, t1a, t1b, HID, 0, NN);
    k_mma_gemm<<<GRID_M, 256, GEMM_SMEM>>>(t1a, t1b, HID, HID, w0 + woff[6], w1 + woff[6],
                                           pb2, 1, 1, nullptr, 0, t2a, t2b, HID, 0, NN);
    // post3: 128 -> 256 in ONE launch (grid.y = 2 N-blocks)
    k_mma_gemm<<<dim3(GRID_M, 2), 256, GEMM_SMEM>>>(t2a, t2b, HID, HID,
                                                    w0 + woff[7], w1 + woff[7],
                                                    pb3, 1, 1, nullptr, 0,
                                                    t3a, t3b, 256, 0, NN);
    // post4: 256 -> 128, fp32 to d_out
    k_mma_gemm<<<GRID_M, 256, GEMM_SMEM>>>(t3a, t3b, 256, 256, w0 + woff[8], w1 + woff[8],
                                           pb4, 0, 0, out, HID, nullptr, nullptr, 0, 0, NN);
}

// round 12
// speedup vs baseline: 1.1579x; 1.0275x over previous
#include <cuda_runtime.h>
#include <cuda_bf16.h>
#include <cstdint>

#define NN 100000
#define NE 1600000
#define HID 128
#define EMB_W 640
#define SCAN_B 98
#define GRID_M 1563           // ceil(NN/64)

// ---------------------------------------------------------------------------
// Static device scratch
// ---------------------------------------------------------------------------
__device__ int   g_deg[NN];
__device__ float g_dinv[NN];
__device__ int   g_rowoff[NN + 1];
__device__ int   g_cursor[NN];
__device__ int   g_bsum[SCAN_B];
__device__ int   g_boff[SCAN_B];
__device__ int   g_csr_src[NE];

__device__ __nv_bfloat16 g_xa0[(size_t)NN * HID];
__device__ __nv_bfloat16 g_xa1[(size_t)NN * HID];
__device__ __nv_bfloat16 g_e0[(size_t)NN * EMB_W];
__device__ __nv_bfloat16 g_e1[(size_t)NN * EMB_W];
__device__ float         g_h[(size_t)NN * HID];
__device__ __nv_bfloat16 g_t1a[(size_t)NN * HID];
__device__ __nv_bfloat16 g_t1b[(size_t)NN * HID];
__device__ __nv_bfloat16 g_t2a[(size_t)NN * HID];
__device__ __nv_bfloat16 g_t2b[(size_t)NN * HID];
__device__ __nv_bfloat16 g_t3a[(size_t)NN * 256];
__device__ __nv_bfloat16 g_t3b[(size_t)NN * 256];
__device__ __nv_bfloat16 g_w0[344064];
__device__ __nv_bfloat16 g_w1[344064];

// ---------------------------------------------------------------------------
// Helpers
// ---------------------------------------------------------------------------
__device__ __forceinline__ uint32_t s2u(const void* p) {
    uint32_t a;
    asm("{ .reg .u64 t; cvta.to.shared.u64 t, %1; cvt.u32.u64 %0, t; }" : "=r"(a) : "l"(p));
    return a;
}

#define SWZ(o) ((o) ^ (((o) >> 3) & 0x70))

__device__ __forceinline__ void cp16(uint32_t s, const void* g, bool v) {
    int sz = v ? 16 : 0;
    asm volatile("cp.async.cg.shared.global [%0], [%1], 16, %2;"
                 :: "r"(s), "l"(g), "r"(sz) : "memory");
}
__device__ __forceinline__ void cp_commit() {
    asm volatile("cp.async.commit_group;" ::: "memory");
}
__device__ __forceinline__ void cp_wait1() {
    asm volatile("cp.async.wait_group 1;" ::: "memory");
}

__device__ __forceinline__ void ldsm_x4(uint32_t* r, uint32_t addr) {
    asm volatile("ldmatrix.sync.aligned.m8n8.x4.shared.b16 {%0,%1,%2,%3}, [%4];"
                 : "=r"(r[0]), "=r"(r[1]), "=r"(r[2]), "=r"(r[3]) : "r"(addr));
}

__device__ __forceinline__ void mma16816(float* d, const uint32_t* a, const uint32_t* b) {
    asm volatile(
        "mma.sync.aligned.m16n8k16.row.col.f32.bf16.bf16.f32 "
        "{%0,%1,%2,%3}, {%4,%5,%6,%7}, {%8,%9}, {%0,%1,%2,%3};"
        : "+f"(d[0]), "+f"(d[1]), "+f"(d[2]), "+f"(d[3])
        : "r"(a[0]), "r"(a[1]), "r"(a[2]), "r"(a[3]), "r"(b[0]), "r"(b[1]));
}

// ---------------------------------------------------------------------------
// CSR build
// ---------------------------------------------------------------------------
__global__ void k_zero_deg() {
    int i = blockIdx.x * blockDim.x + threadIdx.x;
    if (i < NN) g_deg[i] = 0;
}

__global__ void k_hist(const int* __restrict__ ei) {
    int e = blockIdx.x * blockDim.x + threadIdx.x;
    if (e < NE) atomicAdd(&g_deg[ei[NE + e]], 1);
}

__global__ void k_scan1() {
    __shared__ int sh[1024];
    int i = blockIdx.x * 1024 + threadIdx.x;
    int v = (i < NN) ? g_deg[i] : 0;
    sh[threadIdx.x] = v;
    __syncthreads();
    #pragma unroll
    for (int off = 1; off < 1024; off <<= 1) {
        int t = (threadIdx.x >= off) ? sh[threadIdx.x - off] : 0;
        __syncthreads();
        sh[threadIdx.x] += t;
        __syncthreads();
    }
    int incl = sh[threadIdx.x];
    if (i < NN) g_rowoff[i] = incl - v;
    if (threadIdx.x == 1023) g_bsum[blockIdx.x] = incl;
}

__global__ void k_scan2() {
    __shared__ int sh[128];
    int t = threadIdx.x;
    int v = (t < SCAN_B) ? g_bsum[t] : 0;
    sh[t] = v;
    __syncthreads();
    #pragma unroll
    for (int off = 1; off < 128; off <<= 1) {
        int u = (t >= off) ? sh[t - off] : 0;
        __syncthreads();
        sh[t] += u;
        __syncthreads();
    }
    if (t < SCAN_B) g_boff[t] = sh[t] - v;
}

__global__ void k_scan3() {
    int i = blockIdx.x * 1024 + threadIdx.x;
    if (i < NN) {
        int r = g_rowoff[i] + g_boff[blockIdx.x];
        g_rowoff[i] = r;
        g_cursor[i] = r;
        g_dinv[i]   = rsqrtf((float)(g_deg[i] + 1));
    }
    if (i == 0) g_rowoff[NN] = NE;
}

__global__ void k_scatter(const int* __restrict__ ei) {
    int e = blockIdx.x * blockDim.x + threadIdx.x;
    if (e < NE) {
        int src = ei[e];
        int dst = ei[NE + e];
        int pos = atomicAdd(&g_cursor[dst], 1);
        g_csr_src[pos] = src;
    }
}

// ---------------------------------------------------------------------------
// Conversions
// ---------------------------------------------------------------------------
__global__ void k_cvt_x(const float* __restrict__ x) {
    size_t i = (size_t)blockIdx.x * blockDim.x + threadIdx.x;
    if (i < (size_t)NN * HID) {
        float v = x[i];
        __nv_bfloat16 h = __float2bfloat16_rn(v);
        g_xa0[i] = h;
        g_xa1[i] = __float2bfloat16_rn(v - __bfloat162float(h));
    }
}

// All 9 weights: [K x N] fp32 -> transposed split bf16 [N x K], one kernel.
__global__ void k_prep_all(const float* __restrict__ s0, const float* __restrict__ s1,
                           const float* __restrict__ s2, const float* __restrict__ s3,
                           const float* __restrict__ s4, const float* __restrict__ s5,
                           const float* __restrict__ s6, const float* __restrict__ s7,
                           const float* __restrict__ s8)
{
    int b = blockIdx.x;
    const float* src; int K, N, base; size_t off;
    if      (b <   64) { src = s0; K = 128; N = 128; base =    0; off = 0; }
    else if (b <  128) { src = s1; K = 128; N = 128; base =   64; off = 16384; }
    else if (b <  256) { src = s2; K = 256; N = 128; base =  128; off = 32768; }
    else if (b <  448) { src = s3; K = 384; N = 128; base =  256; off = 65536; }
    else if (b <  704) { src = s4; K = 512; N = 128; base =  448; off = 114688; }
    else if (b < 1024) { src = s5; K = 640; N = 128; base =  704; off = 180224; }
    else if (b < 1088) { src = s6; K = 128; N = 128; base = 1024; off = 262144; }
    else if (b < 1216) { src = s7; K = 128; N = 256; base = 1088; off = 278528; }
    else               { src = s8; K = 256; N = 128; base = 1216; off = 311296; }

    int i = (b - base) * 256 + threadIdx.x;
    if (i < K * N) {
        int k = i / N, n = i % N;
        float v = src[i];
        __nv_bfloat16 h = __float2bfloat16_rn(v);
        g_w0[off + (size_t)n * K + k] = h;
        g_w1[off + (size_t)n * K + k] = __float2bfloat16_rn(v - __bfloat162float(h));
    }
}

// ---------------------------------------------------------------------------
// HMMA GEMM (R6/R8 config): C[nrows x (128*gridDim.y)] = act(A @ B^T + bias)
// BM=64, BN=128, BK=64, 256 threads / 8 warps (2x4 grid, 32x32 warp tiles),
// 2-stage cp.async pipeline, 96KB SMEM -> 2 CTAs/SM.
// rowscale: optional per-row fp32 scale applied before act (for GCN pre-scaling).
// ---------------------------------------------------------------------------
#define ST_A0 0
#define ST_A1 8192
#define ST_B0 16384
#define ST_B1 32768
#define STAGE_BYTES 49152
#define GEMM_SMEM (2 * STAGE_BYTES)

__global__ __launch_bounds__(256, 2)
void k_mma_gemm(const __nv_bfloat16* __restrict__ A0,
                const __nv_bfloat16* __restrict__ A1, int lda, int K,
                const __nv_bfloat16* __restrict__ B0,
                const __nv_bfloat16* __restrict__ B1,
                const float* __restrict__ bias,
                const float* __restrict__ rowscale,
                int act, int out_mode,
                float* __restrict__ Cf, int ldcf,
                __nv_bfloat16* __restrict__ C0,
                __nv_bfloat16* __restrict__ C1, int ldcb, int col_off,
                int nrows)
{
    extern __shared__ __align__(1024) char smem[];
    uint32_t sbase = s2u(smem);

    const int tid  = threadIdx.x;
    const int wid  = tid >> 5;
    const int lane = tid & 31;
    const int wm   = wid & 1;          // row block: 32*wm (within 64)
    const int wn   = wid >> 1;         // col block: 32*wn (0..3)
    const int rowBase = blockIdx.x * 64;
    const int nchunks = K >> 6;

    const __nv_bfloat16* B0p = B0 + (size_t)blockIdx.y * 128 * K;
    const __nv_bfloat16* B1p = B1 + (size_t)blockIdx.y * 128 * K;
    const float* biasp = bias ? bias + blockIdx.y * 128 : nullptr;
    const int colBase = col_off + blockIdx.y * 128;

    float acc[2][4][4];
    #pragma unroll
    for (int i = 0; i < 2; i++)
        #pragma unroll
        for (int j = 0; j < 4; j++)
            #pragma unroll
            for (int c = 0; c < 4; c++) acc[i][j][c] = 0.0f;

    auto load_stage = [&](int s, int kc) {
        uint32_t st = sbase + s * STAGE_BYTES;
        #pragma unroll
        for (int i = 0; i < 2; i++) {
            int idx = tid + i * 256;          // 0..511
            int r   = idx >> 3;               // 0..63
            int c16 = (idx & 7) * 16;
            uint32_t sw = SWZ((uint32_t)(r * 128 + c16));
            int  grow = rowBase + r;
            bool v = grow < nrows;
            int  crow = v ? grow : 0;
            size_t abo = ((size_t)crow * lda + (size_t)kc * 64) * 2 + c16;
            cp16(st + ST_A0 + sw, (const char*)A0 + abo, v);
            cp16(st + ST_A1 + sw, (const char*)A1 + abo, v);
        }
        #pragma unroll
        for (int i = 0; i < 4; i++) {
            int idx = tid + i * 256;          // 0..1023
            int r   = idx >> 3;               // 0..127
            int c16 = (idx & 7) * 16;
            uint32_t sw = SWZ((uint32_t)(r * 128 + c16));
            size_t bbo = ((size_t)r * K + (size_t)kc * 64) * 2 + c16;
            cp16(st + ST_B0 + sw, (const char*)B0p + bbo, true);
            cp16(st + ST_B1 + sw, (const char*)B1p + bbo, true);
        }
    };

    load_stage(0, 0);
    cp_commit();

    const int nladd = (lane & 7) + ((lane >> 4) << 3);  // B ldmatrix n offset
    const int kladd = ((lane >> 3) & 1) * 16;           // B ldmatrix k byte offset
    const int arow  = lane & 15;                        // A ldmatrix row offset
    const int akoff = (lane >> 4) * 16;                 // A ldmatrix k byte offset

    for (int kc = 0; kc < nchunks; kc++) {
        if (kc + 1 < nchunks) load_stage((kc + 1) & 1, kc + 1);
        cp_commit();
        cp_wait1();
        __syncthreads();

        uint32_t st = sbase + (kc & 1) * STAGE_BYTES;
        #pragma unroll
        for (int ks = 0; ks < 4; ks++) {
            int kb = ks * 32;
            uint32_t a0f[2][4], a1f[2][4];
            #pragma unroll
            for (int mt = 0; mt < 2; mt++) {
                uint32_t off = SWZ((uint32_t)((wm * 32 + mt * 16 + arow) * 128 + kb + akoff));
                ldsm_x4(a0f[mt], st + ST_A0 + off);
                ldsm_x4(a1f[mt], st + ST_A1 + off);
            }
            uint32_t b0f[2][4], b1f[2][4];
            #pragma unroll
            for (int bt = 0; bt < 2; bt++) {
                uint32_t off = SWZ((uint32_t)((wn * 32 + bt * 16 + nladd) * 128 + kb + kladd));
                ldsm_x4(b0f[bt], st + ST_B0 + off);
                ldsm_x4(b1f[bt], st + ST_B1 + off);
            }
            #pragma unroll
            for (int mt = 0; mt < 2; mt++)
                #pragma unroll
                for (int nt = 0; nt < 4; nt++) {
                    const uint32_t* bp0 = &b0f[nt >> 1][(nt & 1) * 2];
                    const uint32_t* bp1 = &b1f[nt >> 1][(nt & 1) * 2];
                    mma16816(acc[mt][nt], a0f[mt], bp0);   // a_hi * b_hi
                    mma16816(acc[mt][nt], a0f[mt], bp1);   // a_hi * b_lo
                    mma16816(acc[mt][nt], a1f[mt], bp0);   // a_lo * b_hi
                }
        }
        __syncthreads();
    }

    // Epilogue
    #pragma unroll
    for (int mt = 0; mt < 2; mt++) {
        #pragma unroll
        for (int nt = 0; nt < 4; nt++) {
            int row0 = rowBase + wm * 32 + mt * 16 + (lane >> 2);
            int col  = wn * 32 + nt * 8 + (lane & 3) * 2;
            #pragma unroll
            for (int half = 0; half < 2; half++) {
                int row = row0 + half * 8;
                if (row >= nrows) continue;
                float v0 = acc[mt][nt][half * 2 + 0];
                float v1 = acc[mt][nt][half * 2 + 1];
                if (rowscale) { float rs = rowscale[row]; v0 *= rs; v1 *= rs; }
                if (biasp) { v0 += biasp[col]; v1 += biasp[col + 1]; }
                if (act == 1) { v0 = fmaxf(v0, 0.f); v1 = fmaxf(v1, 0.f); }
                else if (act == 2) {
                    v0 = (v0 > 0.f) ? v0 : 0.1f * v0;
                    v1 = (v1 > 0.f) ? v1 : 0.1f * v1;
                }
                if (out_mode == 0) {
                    float2 o; o.x = v0; o.y = v1;
                    *(float2*)(Cf + (size_t)row * ldcf + colBase + col) = o;
                } else {
                    __nv_bfloat16 h0 = __float2bfloat16_rn(v0);
                    __nv_bfloat16 h1 = __float2bfloat16_rn(v1);
                    __nv_bfloat162 p; p.x = h0; p.y = h1;
                    *(__nv_bfloat162*)(C0 + (size_t)row * ldcb + colBase + col) = p;
                    __nv_bfloat162 q;
                    q.x = __float2bfloat16_rn(v0 - __bfloat162float(h0));
                    q.y = __float2bfloat16_rn(v1 - __bfloat162float(h1));
                    *(__nv_bfloat162*)(C1 + (size_t)row * ldcb + colBase + col) = q;
                }
            }
        }
    }
}

// ---------------------------------------------------------------------------
// GCN aggregation: warp per node, 4-edge unroll; bf16-split write into emb.
// scaled=0: h is raw transform output; per-edge weight dinv[s] (layer 1).
// scaled=1: h rows already pre-scaled by dinv (layers 2-4); no per-edge gather.
// ---------------------------------------------------------------------------
__global__ __launch_bounds__(256, 8)
void k_aggregate(const float* __restrict__ bias, int col_off, int scaled)
{
    int warp = threadIdx.x >> 5;
    int lane = threadIdx.x & 31;
    int node = blockIdx.x * 8 + warp;
    if (node >= NN) return;

    const float4* __restrict__ h4 = (const float4*)g_h;

    int beg = g_rowoff[node];
    int end = g_rowoff[node + 1];
    float di = g_dinv[node];

    float4 acc = make_float4(0.f, 0.f, 0.f, 0.f);
    int j = beg;
    if (scaled) {
        for (; j + 4 <= end; j += 4) {
            int s0 = g_csr_src[j];
            int s1 = g_csr_src[j + 1];
            int s2 = g_csr_src[j + 2];
            int s3 = g_csr_src[j + 3];
            float4 v0 = h4[(size_t)s0 * 32 + lane];
            float4 v1 = h4[(size_t)s1 * 32 + lane];
            float4 v2 = h4[(size_t)s2 * 32 + lane];
            float4 v3 = h4[(size_t)s3 * 32 + lane];
            acc.x += v0.x + v1.x + v2.x + v3.x;
            acc.y += v0.y + v1.y + v2.y + v3.y;
            acc.z += v0.z + v1.z + v2.z + v3.z;
            acc.w += v0.w + v1.w + v2.w + v3.w;
        }
        for (; j < end; j++) {
            int s = g_csr_src[j];
            float4 hv = h4[(size_t)s * 32 + lane];
            acc.x += hv.x; acc.y += hv.y; acc.z += hv.z; acc.w += hv.w;
        }
        float4 hs = h4[(size_t)node * 32 + lane];   // already dinv[node]*h
        acc.x = di * (acc.x + hs.x);
        acc.y = di * (acc.y + hs.y);
        acc.z = di * (acc.z + hs.z);
        acc.w = di * (acc.w + hs.w);
    } else {
        for (; j + 4 <= end; j += 4) {
            int s0 = g_csr_src[j];
            int s1 = g_csr_src[j + 1];
            int s2 = g_csr_src[j + 2];
            int s3 = g_csr_src[j + 3];
            float w0 = g_dinv[s0], w1 = g_dinv[s1], w2 = g_dinv[s2], w3 = g_dinv[s3];
            float4 v0 = h4[(size_t)s0 * 32 + lane];
            float4 v1 = h4[(size_t)s1 * 32 + lane];
            float4 v2 = h4[(size_t)s2 * 32 + lane];
            float4 v3 = h4[(size_t)s3 * 32 + lane];
            acc.x += w0 * v0.x + w1 * v1.x + w2 * v2.x + w3 * v3.x;
            acc.y += w0 * v0.y + w1 * v1.y + w2 * v2.y + w3 * v3.y;
            acc.z += w0 * v0.z + w1 * v1.z + w2 * v2.z + w3 * v3.z;
            acc.w += w0 * v0.w + w1 * v1.w + w2 * v2.w + w3 * v3.w;
        }
        for (; j < end; j++) {
            int s = g_csr_src[j];
            float w = g_dinv[s];
            float4 hv = h4[(size_t)s * 32 + lane];
            acc.x += w * hv.x; acc.y += w * hv.y;
            acc.z += w * hv.z; acc.w += w * hv.w;
        }
        float4 hs = h4[(size_t)node * 32 + lane];
        float dii = di * di;
        acc.x = di * acc.x + dii * hs.x;
        acc.y = di * acc.y + dii * hs.y;
        acc.z = di * acc.z + dii * hs.z;
        acc.w = di * acc.w + dii * hs.w;
    }

    float4 b = ((const float4*)bias)[lane];
    float v[4];
    v[0] = fmaxf(acc.x + b.x, 0.f);
    v[1] = fmaxf(acc.y + b.y, 0.f);
    v[2] = fmaxf(acc.z + b.z, 0.f);
    v[3] = fmaxf(acc.w + b.w, 0.f);

    size_t base = (size_t)node * EMB_W + col_off + lane * 4;
    #pragma unroll
    for (int c = 0; c < 4; c += 2) {
        __nv_bfloat16 h0 = __float2bfloat16_rn(v[c]);
        __nv_bfloat16 h1 = __float2bfloat16_rn(v[c + 1]);
        __nv_bfloat162 p; p.x = h0; p.y = h1;
        *(__nv_bfloat162*)(g_e0 + base + c) = p;
        __nv_bfloat162 q;
        q.x = __float2bfloat16_rn(v[c]     - __bfloat162float(h0));
        q.y = __float2bfloat16_rn(v[c + 1] - __bfloat162float(h1));
        *(__nv_bfloat162*)(g_e1 + base + c) = q;
    }
}

// ---------------------------------------------------------------------------
// Launch (R8 structure: CSR on side stream, aggs serial on main)
// ---------------------------------------------------------------------------
extern "C" void kernel_launch(void* const* d_in, const int* in_sizes, int n_in,
                              void* d_out, int out_size)
{
    const float* x   = (const float*)d_in[0];
    const int*   ei  = (const int*)  d_in[1];
    const float* pre_w = (const float*)d_in[2];
    const float* pre_b = (const float*)d_in[3];
    const float* conv_w[4] = { (const float*)d_in[4], (const float*)d_in[6],
                               (const float*)d_in[8], (const float*)d_in[10] };
    const float* conv_b[4] = { (const float*)d_in[5], (const float*)d_in[7],
                               (const float*)d_in[9], (const float*)d_in[11] };
    const float* pw1 = (const float*)d_in[12]; const float* pb1 = (const float*)d_in[13];
    const float* pw2 = (const float*)d_in[14]; const float* pb2 = (const float*)d_in[15];
    const float* pw3 = (const float*)d_in[16]; const float* pb3 = (const float*)d_in[17];
    const float* pw4 = (const float*)d_in[18]; const float* pb4 = (const float*)d_in[19];
    float* out = (float*)d_out;

    __nv_bfloat16 *xa0, *xa1, *e0, *e1, *t1a, *t1b, *t2a, *t2b, *t3a, *t3b, *w0, *w1;
    float *hp, *dinv;
    cudaGetSymbolAddress((void**)&xa0, g_xa0);
    cudaGetSymbolAddress((void**)&xa1, g_xa1);
    cudaGetSymbolAddress((void**)&e0,  g_e0);
    cudaGetSymbolAddress((void**)&e1,  g_e1);
    cudaGetSymbolAddress((void**)&t1a, g_t1a);
    cudaGetSymbolAddress((void**)&t1b, g_t1b);
    cudaGetSymbolAddress((void**)&t2a, g_t2a);
    cudaGetSymbolAddress((void**)&t2b, g_t2b);
    cudaGetSymbolAddress((void**)&t3a, g_t3a);
    cudaGetSymbolAddress((void**)&t3b, g_t3b);
    cudaGetSymbolAddress((void**)&w0,  g_w0);
    cudaGetSymbolAddress((void**)&w1,  g_w1);
    cudaGetSymbolAddress((void**)&hp,  g_h);
    cudaGetSymbolAddress((void**)&dinv, g_dinv);

    cudaFuncSetAttribute(k_mma_gemm, cudaFuncAttributeMaxDynamicSharedMemorySize, GEMM_SMEM);

    static cudaStream_t s_side = nullptr;
    static cudaEvent_t  s_ev1 = nullptr, s_ev2 = nullptr;
    if (s_side == nullptr) {
        cudaStreamCreateWithFlags(&s_side, cudaStreamNonBlocking);
        cudaEventCreateWithFlags(&s_ev1, cudaEventDisableTiming);
        cudaEventCreateWithFlags(&s_ev2, cudaEventDisableTiming);
    }

    const int TB = 256;
    const int nodeBlocks = (NN + TB - 1) / TB;
    const int edgeBlocks = (NE + TB - 1) / TB;
    const size_t woff[9] = { 0, 16384, 32768, 65536, 114688, 180224, 262144, 278528, 311296 };

    // Fork: CSR build on side stream, concurrent with weight prep + early GEMMs.
    cudaEventRecord(s_ev1, 0);
    cudaStreamWaitEvent(s_side, s_ev1, 0);
    k_zero_deg<<<nodeBlocks, TB, 0, s_side>>>();
    k_hist<<<edgeBlocks, TB, 0, s_side>>>(ei);
    k_scan1<<<SCAN_B, 1024, 0, s_side>>>();
    k_scan2<<<1, 128, 0, s_side>>>();
    k_scan3<<<SCAN_B, 1024, 0, s_side>>>();
    k_scatter<<<edgeBlocks, TB, 0, s_side>>>(ei);
    cudaEventRecord(s_ev2, s_side);

    // Main stream: weight prep, cvt, pre GEMM, conv1 GEMM (unscaled h)
    k_prep_all<<<1344, 256>>>(pre_w, conv_w[0], conv_w[1], conv_w[2], conv_w[3],
                              pw1, pw2, pw3, pw4);
    k_cvt_x<<<((size_t)NN * HID + 255) / 256, 256>>>(x);

    k_mma_gemm<<<GRID_M, 256, GEMM_SMEM>>>(xa0, xa1, HID, HID, w0 + woff[0], w1 + woff[0],
                                           pre_b, nullptr, 0, 1, nullptr, 0,
                                           e0, e1, EMB_W, 0, NN);
    k_mma_gemm<<<GRID_M, 256, GEMM_SMEM>>>(e0, e1, EMB_W, HID, w0 + woff[1], w1 + woff[1],
                                           nullptr, nullptr, 0, 0, hp, HID,
                                           nullptr, nullptr, 0, 0, NN);

    // Join: aggregation needs CSR. Layer 1 uses unscaled path.
    cudaStreamWaitEvent(0, s_ev2, 0);
    k_aggregate<<<(NN + 7) / 8, 256>>>(conv_b[0], HID, 0);

    // Layers 2-4: transform writes h pre-scaled by dinv[row]; scaled aggregation.
    for (int l = 1; l < 4; l++) {
        int K = HID * (l + 1);
        k_mma_gemm<<<GRID_M, 256, GEMM_SMEM>>>(e0, e1, EMB_W, K,
                                               w0 + woff[1 + l], w1 + woff[1 + l],
                                               nullptr, dinv, 0, 0, hp, HID,
                                               nullptr, nullptr, 0, 0, NN);
        k_aggregate<<<(NN + 7) / 8, 256>>>(conv_b[l], K, 1);
    }

    // post_mp
    k_mma_gemm<<<GRID_M, 256, GEMM_SMEM>>>(e0, e1, EMB_W, EMB_W, w0 + woff[5], w1 + woff[5],
                                           pb1, nullptr, 2, 1, nullptr, 0,
                                           t1a, t1b, HID, 0, NN);
    k_mma_gemm<<<GRID_M, 256, GEMM_SMEM>>>(t1a, t1b, HID, HID, w0 + woff[6], w1 + woff[6],
                                           pb2, nullptr, 1, 1, nullptr, 0,
                                           t2a, t2b, HID, 0, NN);
    k_mma_gemm<<<dim3(GRID_M, 2), 256, GEMM_SMEM>>>(t2a, t2b, HID, HID,
                                                    w0 + woff[7], w1 + woff[7],
                                                    pb3, nullptr, 1, 1, nullptr, 0,
                                                    t3a, t3b, 256, 0, NN);
    k_mma_gemm<<<GRID_M, 256, GEMM_SMEM>>>(t3a, t3b, 256, 256, w0 + woff[8], w1 + woff[8],
                                           pb4, nullptr, 0, 0, out, HID,
                                           nullptr, nullptr, 0, 0, NN);
}

// round 13
// speedup vs baseline: 1.2512x; 1.0806x over previous
#include <cuda_runtime.h>
#include <cuda_bf16.h>
#include <cstdint>

#define NN 100000
#define NE 1600000
#define HID 128
#define EMB_W 640
#define SCAN_B 98
#define GRID_M 1563           // ceil(NN/64)

// ---------------------------------------------------------------------------
// Static device scratch
// ---------------------------------------------------------------------------
__device__ int   g_deg[NN];
__device__ float g_dinv[NN];
__device__ int   g_rowoff[NN + 1];
__device__ int   g_cursor[NN];
__device__ int   g_bsum[SCAN_B];
__device__ int   g_boff[SCAN_B];
__device__ int   g_csr_src[NE];

__device__ __nv_bfloat16 g_xa0[(size_t)NN * HID];
__device__ __nv_bfloat16 g_xa1[(size_t)NN * HID];
__device__ __nv_bfloat16 g_e0[(size_t)NN * EMB_W];
__device__ __nv_bfloat16 g_e1[(size_t)NN * EMB_W];
__device__ float         g_h[(size_t)NN * HID];
__device__ __nv_bfloat16 g_t1a[(size_t)NN * HID];
__device__ __nv_bfloat16 g_t1b[(size_t)NN * HID];
__device__ __nv_bfloat16 g_t2a[(size_t)NN * HID];
__device__ __nv_bfloat16 g_t2b[(size_t)NN * HID];
__device__ __nv_bfloat16 g_t3a[(size_t)NN * 256];
__device__ __nv_bfloat16 g_t3b[(size_t)NN * 256];
__device__ __nv_bfloat16 g_w0[344064];
__device__ __nv_bfloat16 g_w1[344064];

// ---------------------------------------------------------------------------
// Helpers
// ---------------------------------------------------------------------------
__device__ __forceinline__ uint32_t s2u(const void* p) {
    uint32_t a;
    asm("{ .reg .u64 t; cvta.to.shared.u64 t, %1; cvt.u32.u64 %0, t; }" : "=r"(a) : "l"(p));
    return a;
}

#define SWZ(o) ((o) ^ (((o) >> 3) & 0x70))

__device__ __forceinline__ void cp16(uint32_t s, const void* g, bool v) {
    int sz = v ? 16 : 0;
    asm volatile("cp.async.cg.shared.global [%0], [%1], 16, %2;"
                 :: "r"(s), "l"(g), "r"(sz) : "memory");
}
__device__ __forceinline__ void cp_commit() {
    asm volatile("cp.async.commit_group;" ::: "memory");
}
__device__ __forceinline__ void cp_wait1() {
    asm volatile("cp.async.wait_group 1;" ::: "memory");
}

__device__ __forceinline__ void ldsm_x4(uint32_t* r, uint32_t addr) {
    asm volatile("ldmatrix.sync.aligned.m8n8.x4.shared.b16 {%0,%1,%2,%3}, [%4];"
                 : "=r"(r[0]), "=r"(r[1]), "=r"(r[2]), "=r"(r[3]) : "r"(addr));
}

__device__ __forceinline__ void mma16816(float* d, const uint32_t* a, const uint32_t* b) {
    asm volatile(
        "mma.sync.aligned.m16n8k16.row.col.f32.bf16.bf16.f32 "
        "{%0,%1,%2,%3}, {%4,%5,%6,%7}, {%8,%9}, {%0,%1,%2,%3};"
        : "+f"(d[0]), "+f"(d[1]), "+f"(d[2]), "+f"(d[3])
        : "r"(a[0]), "r"(a[1]), "r"(a[2]), "r"(a[3]), "r"(b[0]), "r"(b[1]));
}

// ---------------------------------------------------------------------------
// CSR build
// ---------------------------------------------------------------------------
__global__ void k_zero_deg() {
    int i = blockIdx.x * blockDim.x + threadIdx.x;
    if (i < NN) g_deg[i] = 0;
}

__global__ void k_hist(const int* __restrict__ ei) {
    int e = blockIdx.x * blockDim.x + threadIdx.x;
    if (e < NE) atomicAdd(&g_deg[ei[NE + e]], 1);
}

__global__ void k_scan1() {
    __shared__ int sh[1024];
    int i = blockIdx.x * 1024 + threadIdx.x;
    int v = (i < NN) ? g_deg[i] : 0;
    sh[threadIdx.x] = v;
    __syncthreads();
    #pragma unroll
    for (int off = 1; off < 1024; off <<= 1) {
        int t = (threadIdx.x >= off) ? sh[threadIdx.x - off] : 0;
        __syncthreads();
        sh[threadIdx.x] += t;
        __syncthreads();
    }
    int incl = sh[threadIdx.x];
    if (i < NN) g_rowoff[i] = incl - v;
    if (threadIdx.x == 1023) g_bsum[blockIdx.x] = incl;
}

__global__ void k_scan2() {
    __shared__ int sh[128];
    int t = threadIdx.x;
    int v = (t < SCAN_B) ? g_bsum[t] : 0;
    sh[t] = v;
    __syncthreads();
    #pragma unroll
    for (int off = 1; off < 128; off <<= 1) {
        int u = (t >= off) ? sh[t - off] : 0;
        __syncthreads();
        sh[t] += u;
        __syncthreads();
    }
    if (t < SCAN_B) g_boff[t] = sh[t] - v;
}

__global__ void k_scan3() {
    int i = blockIdx.x * 1024 + threadIdx.x;
    if (i < NN) {
        int r = g_rowoff[i] + g_boff[blockIdx.x];
        g_rowoff[i] = r;
        g_cursor[i] = r;
        g_dinv[i]   = rsqrtf((float)(g_deg[i] + 1));
    }
    if (i == 0) g_rowoff[NN] = NE;
}

__global__ void k_scatter(const int* __restrict__ ei) {
    int e = blockIdx.x * blockDim.x + threadIdx.x;
    if (e < NE) {
        int src = ei[e];
        int dst = ei[NE + e];
        int pos = atomicAdd(&g_cursor[dst], 1);
        g_csr_src[pos] = src;
    }
}

// ---------------------------------------------------------------------------
// Fused weight prep + x conversion.
// Blocks [0,1344): 9 weights [K x N] fp32 -> transposed split bf16 [N x K].
// Blocks [1344, 1344+50000): x fp32 -> split bf16.
// ---------------------------------------------------------------------------
#define CVT_BLOCKS 50000
__global__ void k_prep_cvt(const float* __restrict__ x,
                           const float* __restrict__ s0, const float* __restrict__ s1,
                           const float* __restrict__ s2, const float* __restrict__ s3,
                           const float* __restrict__ s4, const float* __restrict__ s5,
                           const float* __restrict__ s6, const float* __restrict__ s7,
                           const float* __restrict__ s8)
{
    int b = blockIdx.x;
    if (b >= 1344) {
        size_t i = (size_t)(b - 1344) * 256 + threadIdx.x;
        if (i < (size_t)NN * HID) {
            float v = x[i];
            __nv_bfloat16 h = __float2bfloat16_rn(v);
            g_xa0[i] = h;
            g_xa1[i] = __float2bfloat16_rn(v - __bfloat162float(h));
        }
        return;
    }
    const float* src; int K, N, base; size_t off;
    if      (b <   64) { src = s0; K = 128; N = 128; base =    0; off = 0; }
    else if (b <  128) { src = s1; K = 128; N = 128; base =   64; off = 16384; }
    else if (b <  256) { src = s2; K = 256; N = 128; base =  128; off = 32768; }
    else if (b <  448) { src = s3; K = 384; N = 128; base =  256; off = 65536; }
    else if (b <  704) { src = s4; K = 512; N = 128; base =  448; off = 114688; }
    else if (b < 1024) { src = s5; K = 640; N = 128; base =  704; off = 180224; }
    else if (b < 1088) { src = s6; K = 128; N = 128; base = 1024; off = 262144; }
    else if (b < 1216) { src = s7; K = 128; N = 256; base = 1088; off = 278528; }
    else               { src = s8; K = 256; N = 128; base = 1216; off = 311296; }

    int i = (b - base) * 256 + threadIdx.x;
    if (i < K * N) {
        int k = i / N, n = i % N;
        float v = src[i];
        __nv_bfloat16 h = __float2bfloat16_rn(v);
        g_w0[off + (size_t)n * K + k] = h;
        g_w1[off + (size_t)n * K + k] = __float2bfloat16_rn(v - __bfloat162float(h));
    }
}

// ---------------------------------------------------------------------------
// HMMA GEMM (R6/R8 config): C[nrows x (128*gridDim.y)] = act(A @ B^T + bias)
// BM=64, BN=128, BK=64, 256 threads / 8 warps (2x4 grid, 32x32 warp tiles),
// 2-stage cp.async pipeline, 96KB SMEM -> 2 CTAs/SM.
// out_mode=1 stores go through SMEM staging for fully coalesced 16B row stores.
// ---------------------------------------------------------------------------
#define ST_A0 0
#define ST_A1 8192
#define ST_B0 16384
#define ST_B1 32768
#define STAGE_BYTES 49152
#define GEMM_SMEM (2 * STAGE_BYTES)
// Epilogue staging: 64 rows x 68 bf16x2 (272B, 16B-aligned, bank-rotating pad)
#define EPI_ROWB 272
#define EPI_ARR  (64 * EPI_ROWB)   // 17408 bytes per array

__global__ __launch_bounds__(256, 2)
void k_mma_gemm(const __nv_bfloat16* __restrict__ A0,
                const __nv_bfloat16* __restrict__ A1, int lda, int K,
                const __nv_bfloat16* __restrict__ B0,
                const __nv_bfloat16* __restrict__ B1,
                const float* __restrict__ bias, int act, int out_mode,
                float* __restrict__ Cf, int ldcf,
                __nv_bfloat16* __restrict__ C0,
                __nv_bfloat16* __restrict__ C1, int ldcb, int col_off,
                int nrows)
{
    extern __shared__ __align__(1024) char smem[];
    uint32_t sbase = s2u(smem);

    const int tid  = threadIdx.x;
    const int wid  = tid >> 5;
    const int lane = tid & 31;
    const int wm   = wid & 1;          // row block: 32*wm (within 64)
    const int wn   = wid >> 1;         // col block: 32*wn (0..3)
    const int rowBase = blockIdx.x * 64;
    const int nchunks = K >> 6;

    const __nv_bfloat16* B0p = B0 + (size_t)blockIdx.y * 128 * K;
    const __nv_bfloat16* B1p = B1 + (size_t)blockIdx.y * 128 * K;
    const float* biasp = bias ? bias + blockIdx.y * 128 : nullptr;
    const int colBase = col_off + blockIdx.y * 128;

    float acc[2][4][4];
    #pragma unroll
    for (int i = 0; i < 2; i++)
        #pragma unroll
        for (int j = 0; j < 4; j++)
            #pragma unroll
            for (int c = 0; c < 4; c++) acc[i][j][c] = 0.0f;

    auto load_stage = [&](int s, int kc) {
        uint32_t st = sbase + s * STAGE_BYTES;
        #pragma unroll
        for (int i = 0; i < 2; i++) {
            int idx = tid + i * 256;          // 0..511
            int r   = idx >> 3;               // 0..63
            int c16 = (idx & 7) * 16;
            uint32_t sw = SWZ((uint32_t)(r * 128 + c16));
            int  grow = rowBase + r;
            bool v = grow < nrows;
            int  crow = v ? grow : 0;
            size_t abo = ((size_t)crow * lda + (size_t)kc * 64) * 2 + c16;
            cp16(st + ST_A0 + sw, (const char*)A0 + abo, v);
            cp16(st + ST_A1 + sw, (const char*)A1 + abo, v);
        }
        #pragma unroll
        for (int i = 0; i < 4; i++) {
            int idx = tid + i * 256;          // 0..1023
            int r   = idx >> 3;               // 0..127
            int c16 = (idx & 7) * 16;
            uint32_t sw = SWZ((uint32_t)(r * 128 + c16));
            size_t bbo = ((size_t)r * K + (size_t)kc * 64) * 2 + c16;
            cp16(st + ST_B0 + sw, (const char*)B0p + bbo, true);
            cp16(st + ST_B1 + sw, (const char*)B1p + bbo, true);
        }
    };

    load_stage(0, 0);
    cp_commit();

    const int nladd = (lane & 7) + ((lane >> 4) << 3);  // B ldmatrix n offset
    const int kladd = ((lane >> 3) & 1) * 16;           // B ldmatrix k byte offset
    const int arow  = lane & 15;                        // A ldmatrix row offset
    const int akoff = (lane >> 4) * 16;                 // A ldmatrix k byte offset

    for (int kc = 0; kc < nchunks; kc++) {
        if (kc + 1 < nchunks) load_stage((kc + 1) & 1, kc + 1);
        cp_commit();
        cp_wait1();
        __syncthreads();

        uint32_t st = sbase + (kc & 1) * STAGE_BYTES;
        #pragma unroll
        for (int ks = 0; ks < 4; ks++) {
            int kb = ks * 32;
            uint32_t a0f[2][4], a1f[2][4];
            #pragma unroll
            for (int mt = 0; mt < 2; mt++) {
                uint32_t off = SWZ((uint32_t)((wm * 32 + mt * 16 + arow) * 128 + kb + akoff));
                ldsm_x4(a0f[mt], st + ST_A0 + off);
                ldsm_x4(a1f[mt], st + ST_A1 + off);
            }
            uint32_t b0f[2][4], b1f[2][4];
            #pragma unroll
            for (int bt = 0; bt < 2; bt++) {
                uint32_t off = SWZ((uint32_t)((wn * 32 + bt * 16 + nladd) * 128 + kb + kladd));
                ldsm_x4(b0f[bt], st + ST_B0 + off);
                ldsm_x4(b1f[bt], st + ST_B1 + off);
            }
            #pragma unroll
            for (int mt = 0; mt < 2; mt++)
                #pragma unroll
                for (int nt = 0; nt < 4; nt++) {
                    const uint32_t* bp0 = &b0f[nt >> 1][(nt & 1) * 2];
                    const uint32_t* bp1 = &b1f[nt >> 1][(nt & 1) * 2];
                    mma16816(acc[mt][nt], a0f[mt], bp0);   // a_hi * b_hi
                    mma16816(acc[mt][nt], a0f[mt], bp1);   // a_hi * b_lo
                    mma16816(acc[mt][nt], a1f[mt], bp0);   // a_lo * b_hi
                }
        }
        __syncthreads();
    }

    // Epilogue
    if (out_mode == 0) {
        #pragma unroll
        for (int mt = 0; mt < 2; mt++) {
            #pragma unroll
            for (int nt = 0; nt < 4; nt++) {
                int row0 = rowBase + wm * 32 + mt * 16 + (lane >> 2);
                int col  = wn * 32 + nt * 8 + (lane & 3) * 2;
                #pragma unroll
                for (int half = 0; half < 2; half++) {
                    int row = row0 + half * 8;
                    if (row >= nrows) continue;
                    float v0 = acc[mt][nt][half * 2 + 0];
                    float v1 = acc[mt][nt][half * 2 + 1];
                    if (biasp) { v0 += biasp[col]; v1 += biasp[col + 1]; }
                    if (act == 1) { v0 = fmaxf(v0, 0.f); v1 = fmaxf(v1, 0.f); }
                    else if (act == 2) {
                        v0 = (v0 > 0.f) ? v0 : 0.1f * v0;
                        v1 = (v1 > 0.f) ? v1 : 0.1f * v1;
                    }
                    float2 o; o.x = v0; o.y = v1;
                    *(float2*)(Cf + (size_t)row * ldcf + colBase + col) = o;
                }
            }
        }
    } else {
        // Stage bf16-split outputs in SMEM, then store coalesced full rows.
        char* ep0 = smem;
        char* ep1 = smem + EPI_ARR;
        #pragma unroll
        for (int mt = 0; mt < 2; mt++) {
            #pragma unroll
            for (int nt = 0; nt < 4; nt++) {
                int col = wn * 32 + nt * 8 + (lane & 3) * 2;
                #pragma unroll
                for (int half = 0; half < 2; half++) {
                    int rl = wm * 32 + mt * 16 + (lane >> 2) + half * 8;
                    float v0 = acc[mt][nt][half * 2 + 0];
                    float v1 = acc[mt][nt][half * 2 + 1];
                    if (biasp) { v0 += biasp[col]; v1 += biasp[col + 1]; }
                    if (act == 1) { v0 = fmaxf(v0, 0.f); v1 = fmaxf(v1, 0.f); }
                    else if (act == 2) {
                        v0 = (v0 > 0.f) ? v0 : 0.1f * v0;
                        v1 = (v1 > 0.f) ? v1 : 0.1f * v1;
                    }
                    __nv_bfloat16 h0 = __float2bfloat16_rn(v0);
                    __nv_bfloat16 h1 = __float2bfloat16_rn(v1);
                    __nv_bfloat162 p; p.x = h0; p.y = h1;
                    __nv_bfloat162 q;
                    q.x = __float2bfloat16_rn(v0 - __bfloat162float(h0));
                    q.y = __float2bfloat16_rn(v1 - __bfloat162float(h1));
                    *(__nv_bfloat162*)(ep0 + rl * EPI_ROWB + (col >> 1) * 4) = p;
                    *(__nv_bfloat162*)(ep1 + rl * EPI_ROWB + (col >> 1) * 4) = q;
                }
            }
        }
        __syncthreads();
        // 64 rows x 16 chunks of 16B (= 256B of data per row)
        #pragma unroll
        for (int it = 0; it < 4; it++) {
            int i  = tid + it * 256;          // 0..1023
            int r  = i >> 4;
            int ck = (i & 15) * 16;
            int grow = rowBase + r;
            if (grow < nrows) {
                uint4 v0 = *(uint4*)(ep0 + r * EPI_ROWB + ck);
                uint4 v1 = *(uint4*)(ep1 + r * EPI_ROWB + ck);
                char* d0 = (char*)(C0 + (size_t)grow * ldcb + colBase) + ck;
                char* d1 = (char*)(C1 + (size_t)grow * ldcb + colBase) + ck;
                *(uint4*)d0 = v0;
                *(uint4*)d1 = v1;
            }
        }
    }
}

// ---------------------------------------------------------------------------
// GCN aggregation: warp per node, 4-edge unroll; bf16-split write into emb
// ---------------------------------------------------------------------------
__global__ __launch_bounds__(256, 8)
void k_aggregate(const float* __restrict__ bias, int col_off)
{
    int warp = threadIdx.x >> 5;
    int lane = threadIdx.x & 31;
    int node = blockIdx.x * 8 + warp;
    if (node >= NN) return;

    const float4* __restrict__ h4 = (const float4*)g_h;

    int beg = g_rowoff[node];
    int end = g_rowoff[node + 1];
    float di = g_dinv[node];

    float4 acc = make_float4(0.f, 0.f, 0.f, 0.f);
    int j = beg;
    for (; j + 4 <= end; j += 4) {
        int s0 = g_csr_src[j];
        int s1 = g_csr_src[j + 1];
        int s2 = g_csr_src[j + 2];
        int s3 = g_csr_src[j + 3];
        float w0 = g_dinv[s0], w1 = g_dinv[s1], w2 = g_dinv[s2], w3 = g_dinv[s3];
        float4 v0 = h4[(size_t)s0 * 32 + lane];
        float4 v1 = h4[(size_t)s1 * 32 + lane];
        float4 v2 = h4[(size_t)s2 * 32 + lane];
        float4 v3 = h4[(size_t)s3 * 32 + lane];
        acc.x += w0 * v0.x + w1 * v1.x + w2 * v2.x + w3 * v3.x;
        acc.y += w0 * v0.y + w1 * v1.y + w2 * v2.y + w3 * v3.y;
        acc.z += w0 * v0.z + w1 * v1.z + w2 * v2.z + w3 * v3.z;
        acc.w += w0 * v0.w + w1 * v1.w + w2 * v2.w + w3 * v3.w;
    }
    for (; j < end; j++) {
        int s = g_csr_src[j];
        float w = g_dinv[s];
        float4 hv = h4[(size_t)s * 32 + lane];
        acc.x += w * hv.x; acc.y += w * hv.y;
        acc.z += w * hv.z; acc.w += w * hv.w;
    }
    float4 hs = h4[(size_t)node * 32 + lane];
    float dii = di * di;
    acc.x = di * acc.x + dii * hs.x;
    acc.y = di * acc.y + dii * hs.y;
    acc.z = di * acc.z + dii * hs.z;
    acc.w = di * acc.w + dii * hs.w;

    float4 b = ((const float4*)bias)[lane];
    float v[4];
    v[0] = fmaxf(acc.x + b.x, 0.f);
    v[1] = fmaxf(acc.y + b.y, 0.f);
    v[2] = fmaxf(acc.z + b.z, 0.f);
    v[3] = fmaxf(acc.w + b.w, 0.f);

    size_t base = (size_t)node * EMB_W + col_off + lane * 4;
    #pragma unroll
    for (int c = 0; c < 4; c += 2) {
        __nv_bfloat16 h0 = __float2bfloat16_rn(v[c]);
        __nv_bfloat16 h1 = __float2bfloat16_rn(v[c + 1]);
        __nv_bfloat162 p; p.x = h0; p.y = h1;
        *(__nv_bfloat162*)(g_e0 + base + c) = p;
        __nv_bfloat162 q;
        q.x = __float2bfloat16_rn(v[c]     - __bfloat162float(h0));
        q.y = __float2bfloat16_rn(v[c + 1] - __bfloat162float(h1));
        *(__nv_bfloat162*)(g_e1 + base + c) = q;
    }
}

// ---------------------------------------------------------------------------
// Launch (R8 structure: CSR on side stream, aggs serial on main)
// ---------------------------------------------------------------------------
extern "C" void kernel_launch(void* const* d_in, const int* in_sizes, int n_in,
                              void* d_out, int out_size)
{
    const float* x   = (const float*)d_in[0];
    const int*   ei  = (const int*)  d_in[1];
    const float* pre_w = (const float*)d_in[2];
    const float* pre_b = (const float*)d_in[3];
    const float* conv_w[4] = { (const float*)d_in[4], (const float*)d_in[6],
                               (const float*)d_in[8], (const float*)d_in[10] };
    const float* conv_b[4] = { (const float*)d_in[5], (const float*)d_in[7],
                               (const float*)d_in[9], (const float*)d_in[11] };
    const float* pw1 = (const float*)d_in[12]; const float* pb1 = (const float*)d_in[13];
    const float* pw2 = (const float*)d_in[14]; const float* pb2 = (const float*)d_in[15];
    const float* pw3 = (const float*)d_in[16]; const float* pb3 = (const float*)d_in[17];
    const float* pw4 = (const float*)d_in[18]; const float* pb4 = (const float*)d_in[19];
    float* out = (float*)d_out;

    __nv_bfloat16 *xa0, *xa1, *e0, *e1, *t1a, *t1b, *t2a, *t2b, *t3a, *t3b, *w0, *w1;
    float* hp;
    cudaGetSymbolAddress((void**)&xa0, g_xa0);
    cudaGetSymbolAddress((void**)&xa1, g_xa1);
    cudaGetSymbolAddress((void**)&e0,  g_e0);
    cudaGetSymbolAddress((void**)&e1,  g_e1);
    cudaGetSymbolAddress((void**)&t1a, g_t1a);
    cudaGetSymbolAddress((void**)&t1b, g_t1b);
    cudaGetSymbolAddress((void**)&t2a, g_t2a);
    cudaGetSymbolAddress((void**)&t2b, g_t2b);
    cudaGetSymbolAddress((void**)&t3a, g_t3a);
    cudaGetSymbolAddress((void**)&t3b, g_t3b);
    cudaGetSymbolAddress((void**)&w0,  g_w0);
    cudaGetSymbolAddress((void**)&w1,  g_w1);
    cudaGetSymbolAddress((void**)&hp,  g_h);

    cudaFuncSetAttribute(k_mma_gemm, cudaFuncAttributeMaxDynamicSharedMemorySize, GEMM_SMEM);

    static cudaStream_t s_side = nullptr;
    static cudaEvent_t  s_ev1 = nullptr, s_ev2 = nullptr;
    if (s_side == nullptr) {
        cudaStreamCreateWithFlags(&s_side, cudaStreamNonBlocking);
        cudaEventCreateWithFlags(&s_ev1, cudaEventDisableTiming);
        cudaEventCreateWithFlags(&s_ev2, cudaEventDisableTiming);
    }

    const int TB = 256;
    const int nodeBlocks = (NN + TB - 1) / TB;
    const int edgeBlocks = (NE + TB - 1) / TB;
    const size_t woff[9] = { 0, 16384, 32768, 65536, 114688, 180224, 262144, 278528, 311296 };

    // Fork: CSR build on side stream, concurrent with weight prep + early GEMMs.
    cudaEventRecord(s_ev1, 0);
    cudaStreamWaitEvent(s_side, s_ev1, 0);
    k_zero_deg<<<nodeBlocks, TB, 0, s_side>>>();
    k_hist<<<edgeBlocks, TB, 0, s_side>>>(ei);
    k_scan1<<<SCAN_B, 1024, 0, s_side>>>();
    k_scan2<<<1, 128, 0, s_side>>>();
    k_scan3<<<SCAN_B, 1024, 0, s_side>>>();
    k_scatter<<<edgeBlocks, TB, 0, s_side>>>(ei);
    cudaEventRecord(s_ev2, s_side);

    // Main stream: fused weight prep + x conversion, then GEMMs
    k_prep_cvt<<<1344 + CVT_BLOCKS, 256>>>(x, pre_w, conv_w[0], conv_w[1], conv_w[2],
                                           conv_w[3], pw1, pw2, pw3, pw4);

    k_mma_gemm<<<GRID_M, 256, GEMM_SMEM>>>(xa0, xa1, HID, HID, w0 + woff[0], w1 + woff[0],
                                           pre_b, 0, 1, nullptr, 0, e0, e1, EMB_W, 0, NN);
    k_mma_gemm<<<GRID_M, 256, GEMM_SMEM>>>(e0, e1, EMB_W, HID, w0 + woff[1], w1 + woff[1],
                                           nullptr, 0, 0, hp, HID,
                                           nullptr, nullptr, 0, 0, NN);

    // Join: aggregation needs CSR
    cudaStreamWaitEvent(0, s_ev2, 0);
    k_aggregate<<<(NN + 7) / 8, 256>>>(conv_b[0], HID);

    // Layers 2-4
    for (int l = 1; l < 4; l++) {
        int K = HID * (l + 1);
        k_mma_gemm<<<GRID_M, 256, GEMM_SMEM>>>(e0, e1, EMB_W, K,
                                               w0 + woff[1 + l], w1 + woff[1 + l],
                                               nullptr, 0, 0, hp, HID,
                                               nullptr, nullptr, 0, 0, NN);
        k_aggregate<<<(NN + 7) / 8, 256>>>(conv_b[l], K);
    }

    // post_mp
    k_mma_gemm<<<GRID_M, 256, GEMM_SMEM>>>(e0, e1, EMB_W, EMB_W, w0 + woff[5], w1 + woff[5],
                                           pb1, 2, 1, nullptr, 0, t1a, t1b, HID, 0, NN);
    k_mma_gemm<<<GRID_M, 256, GEMM_SMEM>>>(t1a, t1b, HID, HID, w0 + woff[6], w1 + woff[6],
                                           pb2, 1, 1, nullptr, 0, t2a, t2b, HID, 0, NN);
    // post3: 128 -> 256 in ONE launch (grid.y = 2 N-blocks)
    k_mma_gemm<<<dim3(GRID_M, 2), 256, GEMM_SMEM>>>(t2a, t2b, HID, HID,
                                                    w0 + woff[7], w1 + woff[7],
                                                    pb3, 1, 1, nullptr, 0,
                                                    t3a, t3b, 256, 0, NN);
    // post4: 256 -> 128, fp32 to d_out
    k_mma_gemm<<<GRID_M, 256, GEMM_SMEM>>>(t3a, t3b, 256, 256, w0 + woff[8], w1 + woff[8],
                                           pb4, 0, 0, out, HID, nullptr, nullptr, 0, 0, NN);
}

// round 14
// speedup vs baseline: 1.2528x; 1.0012x over previous
#include <cuda_runtime.h>
#include <cuda_bf16.h>
#include <cstdint>

#define NN 100000
#define NE 1600000
#define HID 128
#define EMB_W 640
#define SCAN_B 98
#define GRID_M 1563           // ceil(NN/64)

// ---------------------------------------------------------------------------
// Static device scratch
// ---------------------------------------------------------------------------
__device__ int   g_deg[NN];
__device__ float g_dinv[NN];
__device__ int   g_rowoff[NN + 1];
__device__ int   g_cursor[NN];
__device__ int   g_bsum[SCAN_B];
__device__ int   g_boff[SCAN_B];
__device__ int   g_csr_src[NE];

__device__ __nv_bfloat16 g_xa0[(size_t)NN * HID];
__device__ __nv_bfloat16 g_xa1[(size_t)NN * HID];
__device__ __nv_bfloat16 g_e0[(size_t)NN * EMB_W];
__device__ __nv_bfloat16 g_e1[(size_t)NN * EMB_W];
__device__ float         g_h[(size_t)NN * HID];
__device__ __nv_bfloat16 g_t1a[(size_t)NN * HID];
__device__ __nv_bfloat16 g_t1b[(size_t)NN * HID];
__device__ __nv_bfloat16 g_t2a[(size_t)NN * HID];
__device__ __nv_bfloat16 g_t2b[(size_t)NN * HID];
__device__ __nv_bfloat16 g_t3a[(size_t)NN * 256];
__device__ __nv_bfloat16 g_t3b[(size_t)NN * 256];
__device__ __nv_bfloat16 g_w0[344064];
__device__ __nv_bfloat16 g_w1[344064];

// ---------------------------------------------------------------------------
// Helpers
// ---------------------------------------------------------------------------
__device__ __forceinline__ uint32_t s2u(const void* p) {
    uint32_t a;
    asm("{ .reg .u64 t; cvta.to.shared.u64 t, %1; cvt.u32.u64 %0, t; }" : "=r"(a) : "l"(p));
    return a;
}

#define SWZ(o) ((o) ^ (((o) >> 3) & 0x70))

__device__ __forceinline__ void cp16(uint32_t s, const void* g, bool v) {
    int sz = v ? 16 : 0;
    asm volatile("cp.async.cg.shared.global [%0], [%1], 16, %2;"
                 :: "r"(s), "l"(g), "r"(sz) : "memory");
}
__device__ __forceinline__ void cp_commit() {
    asm volatile("cp.async.commit_group;" ::: "memory");
}
__device__ __forceinline__ void cp_wait1() {
    asm volatile("cp.async.wait_group 1;" ::: "memory");
}

__device__ __forceinline__ void ldsm_x4(uint32_t* r, uint32_t addr) {
    asm volatile("ldmatrix.sync.aligned.m8n8.x4.shared.b16 {%0,%1,%2,%3}, [%4];"
                 : "=r"(r[0]), "=r"(r[1]), "=r"(r[2]), "=r"(r[3]) : "r"(addr));
}

__device__ __forceinline__ void mma16816(float* d, const uint32_t* a, const uint32_t* b) {
    asm volatile(
        "mma.sync.aligned.m16n8k16.row.col.f32.bf16.bf16.f32 "
        "{%0,%1,%2,%3}, {%4,%5,%6,%7}, {%8,%9}, {%0,%1,%2,%3};"
        : "+f"(d[0]), "+f"(d[1]), "+f"(d[2]), "+f"(d[3])
        : "r"(a[0]), "r"(a[1]), "r"(a[2]), "r"(a[3]), "r"(b[0]), "r"(b[1]));
}

// ---------------------------------------------------------------------------
// CSR build
// ---------------------------------------------------------------------------
__global__ void k_zero_deg() {
    int i = blockIdx.x * blockDim.x + threadIdx.x;
    if (i < NN) g_deg[i] = 0;
}

__global__ void k_hist(const int* __restrict__ ei) {
    int e = blockIdx.x * blockDim.x + threadIdx.x;
    if (e < NE) atomicAdd(&g_deg[ei[NE + e]], 1);
}

__global__ void k_scan1() {
    __shared__ int sh[1024];
    int i = blockIdx.x * 1024 + threadIdx.x;
    int v = (i < NN) ? g_deg[i] : 0;
    sh[threadIdx.x] = v;
    __syncthreads();
    #pragma unroll
    for (int off = 1; off < 1024; off <<= 1) {
        int t = (threadIdx.x >= off) ? sh[threadIdx.x - off] : 0;
        __syncthreads();
        sh[threadIdx.x] += t;
        __syncthreads();
    }
    int incl = sh[threadIdx.x];
    if (i < NN) g_rowoff[i] = incl - v;
    if (threadIdx.x == 1023) g_bsum[blockIdx.x] = incl;
}

__global__ void k_scan2() {
    __shared__ int sh[128];
    int t = threadIdx.x;
    int v = (t < SCAN_B) ? g_bsum[t] : 0;
    sh[t] = v;
    __syncthreads();
    #pragma unroll
    for (int off = 1; off < 128; off <<= 1) {
        int u = (t >= off) ? sh[t - off] : 0;
        __syncthreads();
        sh[t] += u;
        __syncthreads();
    }
    if (t < SCAN_B) g_boff[t] = sh[t] - v;
}

__global__ void k_scan3() {
    int i = blockIdx.x * 1024 + threadIdx.x;
    if (i < NN) {
        int r = g_rowoff[i] + g_boff[blockIdx.x];
        g_rowoff[i] = r;
        g_cursor[i] = r;
        g_dinv[i]   = rsqrtf((float)(g_deg[i] + 1));
    }
    if (i == 0) g_rowoff[NN] = NE;
}

__global__ void k_scatter(const int* __restrict__ ei) {
    int e = blockIdx.x * blockDim.x + threadIdx.x;
    if (e < NE) {
        int src = ei[e];
        int dst = ei[NE + e];
        int pos = atomicAdd(&g_cursor[dst], 1);
        g_csr_src[pos] = src;
    }
}

// ---------------------------------------------------------------------------
// Fused weight prep + x conversion.
// ---------------------------------------------------------------------------
#define CVT_BLOCKS 50000
__global__ void k_prep_cvt(const float* __restrict__ x,
                           const float* __restrict__ s0, const float* __restrict__ s1,
                           const float* __restrict__ s2, const float* __restrict__ s3,
                           const float* __restrict__ s4, const float* __restrict__ s5,
                           const float* __restrict__ s6, const float* __restrict__ s7,
                           const float* __restrict__ s8)
{
    int b = blockIdx.x;
    if (b >= 1344) {
        size_t i = (size_t)(b - 1344) * 256 + threadIdx.x;
        if (i < (size_t)NN * HID) {
            float v = x[i];
            __nv_bfloat16 h = __float2bfloat16_rn(v);
            g_xa0[i] = h;
            g_xa1[i] = __float2bfloat16_rn(v - __bfloat162float(h));
        }
        return;
    }
    const float* src; int K, N, base; size_t off;
    if      (b <   64) { src = s0; K = 128; N = 128; base =    0; off = 0; }
    else if (b <  128) { src = s1; K = 128; N = 128; base =   64; off = 16384; }
    else if (b <  256) { src = s2; K = 256; N = 128; base =  128; off = 32768; }
    else if (b <  448) { src = s3; K = 384; N = 128; base =  256; off = 65536; }
    else if (b <  704) { src = s4; K = 512; N = 128; base =  448; off = 114688; }
    else if (b < 1024) { src = s5; K = 640; N = 128; base =  704; off = 180224; }
    else if (b < 1088) { src = s6; K = 128; N = 128; base = 1024; off = 262144; }
    else if (b < 1216) { src = s7; K = 128; N = 256; base = 1088; off = 278528; }
    else               { src = s8; K = 256; N = 128; base = 1216; off = 311296; }

    int i = (b - base) * 256 + threadIdx.x;
    if (i < K * N) {
        int k = i / N, n = i % N;
        float v = src[i];
        __nv_bfloat16 h = __float2bfloat16_rn(v);
        g_w0[off + (size_t)n * K + k] = h;
        g_w1[off + (size_t)n * K + k] = __float2bfloat16_rn(v - __bfloat162float(h));
    }
}

// ---------------------------------------------------------------------------
// HMMA GEMM: C[nrows x (128*gridDim.y)] = act(A @ B^T + bias)
// BM=64, BN=128, BK=64, 128 threads / 4 warps, warp tile 64x32 (1x4 grid):
// B fragments loaded once per warp (no wm duplication) -> 25% less LDSM.
// 2-stage cp.async pipeline, 96KB SMEM -> 2 CTAs/SM.
// out_mode=1 stores staged through SMEM for coalesced 16B row stores.
// ---------------------------------------------------------------------------
#define ST_A0 0
#define ST_A1 8192
#define ST_B0 16384
#define ST_B1 32768
#define STAGE_BYTES 49152
#define GEMM_SMEM (2 * STAGE_BYTES)
#define EPI_ROWB 272
#define EPI_ARR  (64 * EPI_ROWB)

__global__ __launch_bounds__(128, 2)
void k_mma_gemm(const __nv_bfloat16* __restrict__ A0,
                const __nv_bfloat16* __restrict__ A1, int lda, int K,
                const __nv_bfloat16* __restrict__ B0,
                const __nv_bfloat16* __restrict__ B1,
                const float* __restrict__ bias, int act, int out_mode,
                float* __restrict__ Cf, int ldcf,
                __nv_bfloat16* __restrict__ C0,
                __nv_bfloat16* __restrict__ C1, int ldcb, int col_off,
                int nrows)
{
    extern __shared__ __align__(1024) char smem[];
    uint32_t sbase = s2u(smem);

    const int tid  = threadIdx.x;
    const int wn   = tid >> 5;         // warp 0..3 -> col block 32*wn
    const int lane = tid & 31;
    const int rowBase = blockIdx.x * 64;
    const int nchunks = K >> 6;

    const __nv_bfloat16* B0p = B0 + (size_t)blockIdx.y * 128 * K;
    const __nv_bfloat16* B1p = B1 + (size_t)blockIdx.y * 128 * K;
    const float* biasp = bias ? bias + blockIdx.y * 128 : nullptr;
    const int colBase = col_off + blockIdx.y * 128;

    float acc[4][4][4];
    #pragma unroll
    for (int i = 0; i < 4; i++)
        #pragma unroll
        for (int j = 0; j < 4; j++)
            #pragma unroll
            for (int c = 0; c < 4; c++) acc[i][j][c] = 0.0f;

    auto load_stage = [&](int s, int kc) {
        uint32_t st = sbase + s * STAGE_BYTES;
        // A tiles: 64 rows x 64 bf16 (128B rows) hi+lo: 512 chunk-pairs / 128 thr
        #pragma unroll
        for (int i = 0; i < 4; i++) {
            int idx = tid + i * 128;          // 0..511
            int r   = idx >> 3;               // 0..63
            int c16 = (idx & 7) * 16;
            uint32_t sw = SWZ((uint32_t)(r * 128 + c16));
            int  grow = rowBase + r;
            bool v = grow < nrows;
            int  crow = v ? grow : 0;
            size_t abo = ((size_t)crow * lda + (size_t)kc * 64) * 2 + c16;
            cp16(st + ST_A0 + sw, (const char*)A0 + abo, v);
            cp16(st + ST_A1 + sw, (const char*)A1 + abo, v);
        }
        // B tiles: 128 rows x 64 bf16 hi+lo: 1024 chunk-pairs / 128 thr
        #pragma unroll
        for (int i = 0; i < 8; i++) {
            int idx = tid + i * 128;          // 0..1023
            int r   = idx >> 3;               // 0..127
            int c16 = (idx & 7) * 16;
            uint32_t sw = SWZ((uint32_t)(r * 128 + c16));
            size_t bbo = ((size_t)r * K + (size_t)kc * 64) * 2 + c16;
            cp16(st + ST_B0 + sw, (const char*)B0p + bbo, true);
            cp16(st + ST_B1 + sw, (const char*)B1p + bbo, true);
        }
    };

    load_stage(0, 0);
    cp_commit();

    const int nladd = (lane & 7) + ((lane >> 4) << 3);  // B ldmatrix n offset
    const int kladd = ((lane >> 3) & 1) * 16;           // B ldmatrix k byte offset
    const int arow  = lane & 15;                        // A ldmatrix row offset
    const int akoff = (lane >> 4) * 16;                 // A ldmatrix k byte offset

    for (int kc = 0; kc < nchunks; kc++) {
        if (kc + 1 < nchunks) load_stage((kc + 1) & 1, kc + 1);
        cp_commit();
        cp_wait1();
        __syncthreads();

        uint32_t st = sbase + (kc & 1) * STAGE_BYTES;
        #pragma unroll
        for (int ks = 0; ks < 4; ks++) {
            int kb = ks * 32;
            uint32_t a0f[4][4], a1f[4][4];
            #pragma unroll
            for (int mt = 0; mt < 4; mt++) {
                uint32_t off = SWZ((uint32_t)((mt * 16 + arow) * 128 + kb + akoff));
                ldsm_x4(a0f[mt], st + ST_A0 + off);
                ldsm_x4(a1f[mt], st + ST_A1 + off);
            }
            uint32_t b0f[2][4], b1f[2][4];
            #pragma unroll
            for (int bt = 0; bt < 2; bt++) {
                uint32_t off = SWZ((uint32_t)((wn * 32 + bt * 16 + nladd) * 128 + kb + kladd));
                ldsm_x4(b0f[bt], st + ST_B0 + off);
                ldsm_x4(b1f[bt], st + ST_B1 + off);
            }
            #pragma unroll
            for (int mt = 0; mt < 4; mt++)
                #pragma unroll
                for (int nt = 0; nt < 4; nt++) {
                    const uint32_t* bp0 = &b0f[nt >> 1][(nt & 1) * 2];
                    const uint32_t* bp1 = &b1f[nt >> 1][(nt & 1) * 2];
                    mma16816(acc[mt][nt], a0f[mt], bp0);   // a_hi * b_hi
                    mma16816(acc[mt][nt], a0f[mt], bp1);   // a_hi * b_lo
                    mma16816(acc[mt][nt], a1f[mt], bp0);   // a_lo * b_hi
                }
        }
        __syncthreads();
    }

    // Epilogue
    if (out_mode == 0) {
        #pragma unroll
        for (int mt = 0; mt < 4; mt++) {
            #pragma unroll
            for (int nt = 0; nt < 4; nt++) {
                int row0 = rowBase + mt * 16 + (lane >> 2);
                int col  = wn * 32 + nt * 8 + (lane & 3) * 2;
                #pragma unroll
                for (int half = 0; half < 2; half++) {
                    int row = row0 + half * 8;
                    if (row >= nrows) continue;
                    float v0 = acc[mt][nt][half * 2 + 0];
                    float v1 = acc[mt][nt][half * 2 + 1];
                    if (biasp) { v0 += biasp[col]; v1 += biasp[col + 1]; }
                    if (act == 1) { v0 = fmaxf(v0, 0.f); v1 = fmaxf(v1, 0.f); }
                    else if (act == 2) {
                        v0 = (v0 > 0.f) ? v0 : 0.1f * v0;
                        v1 = (v1 > 0.f) ? v1 : 0.1f * v1;
                    }
                    float2 o; o.x = v0; o.y = v1;
                    *(float2*)(Cf + (size_t)row * ldcf + colBase + col) = o;
                }
            }
        }
    } else {
        char* ep0 = smem;
        char* ep1 = smem + EPI_ARR;
        #pragma unroll
        for (int mt = 0; mt < 4; mt++) {
            #pragma unroll
            for (int nt = 0; nt < 4; nt++) {
                int col = wn * 32 + nt * 8 + (lane & 3) * 2;
                #pragma unroll
                for (int half = 0; half < 2; half++) {
                    int rl = mt * 16 + (lane >> 2) + half * 8;
                    float v0 = acc[mt][nt][half * 2 + 0];
                    float v1 = acc[mt][nt][half * 2 + 1];
                    if (biasp) { v0 += biasp[col]; v1 += biasp[col + 1]; }
                    if (act == 1) { v0 = fmaxf(v0, 0.f); v1 = fmaxf(v1, 0.f); }
                    else if (act == 2) {
                        v0 = (v0 > 0.f) ? v0 : 0.1f * v0;
                        v1 = (v1 > 0.f) ? v1 : 0.1f * v1;
                    }
                    __nv_bfloat16 h0 = __float2bfloat16_rn(v0);
                    __nv_bfloat16 h1 = __float2bfloat16_rn(v1);
                    __nv_bfloat162 p; p.x = h0; p.y = h1;
                    __nv_bfloat162 q;
                    q.x = __float2bfloat16_rn(v0 - __bfloat162float(h0));
                    q.y = __float2bfloat16_rn(v1 - __bfloat162float(h1));
                    *(__nv_bfloat162*)(ep0 + rl * EPI_ROWB + (col >> 1) * 4) = p;
                    *(__nv_bfloat162*)(ep1 + rl * EPI_ROWB + (col >> 1) * 4) = q;
                }
            }
        }
        __syncthreads();
        // 64 rows x 16 chunks of 16B, 1024 chunks / 128 threads = 8 iters
        #pragma unroll
        for (int it = 0; it < 8; it++) {
            int i  = tid + it * 128;
            int r  = i >> 4;
            int ck = (i & 15) * 16;
            int grow = rowBase + r;
            if (grow < nrows) {
                uint4 v0 = *(uint4*)(ep0 + r * EPI_ROWB + ck);
                uint4 v1 = *(uint4*)(ep1 + r * EPI_ROWB + ck);
                char* d0 = (char*)(C0 + (size_t)grow * ldcb + colBase) + ck;
                char* d1 = (char*)(C1 + (size_t)grow * ldcb + colBase) + ck;
                *(uint4*)d0 = v0;
                *(uint4*)d1 = v1;
            }
        }
    }
}

// ---------------------------------------------------------------------------
// GCN aggregation: warp per node, 4-edge unroll; bf16-split write into emb
// ---------------------------------------------------------------------------
__global__ __launch_bounds__(256, 8)
void k_aggregate(const float* __restrict__ bias, int col_off)
{
    int warp = threadIdx.x >> 5;
    int lane = threadIdx.x & 31;
    int node = blockIdx.x * 8 + warp;
    if (node >= NN) return;

    const float4* __restrict__ h4 = (const float4*)g_h;

    int beg = g_rowoff[node];
    int end = g_rowoff[node + 1];
    float di = g_dinv[node];

    float4 acc = make_float4(0.f, 0.f, 0.f, 0.f);
    int j = beg;
    for (; j + 4 <= end; j += 4) {
        int s0 = g_csr_src[j];
        int s1 = g_csr_src[j + 1];
        int s2 = g_csr_src[j + 2];
        int s3 = g_csr_src[j + 3];
        float w0 = g_dinv[s0], w1 = g_dinv[s1], w2 = g_dinv[s2], w3 = g_dinv[s3];
        float4 v0 = h4[(size_t)s0 * 32 + lane];
        float4 v1 = h4[(size_t)s1 * 32 + lane];
        float4 v2 = h4[(size_t)s2 * 32 + lane];
        float4 v3 = h4[(size_t)s3 * 32 + lane];
        acc.x += w0 * v0.x + w1 * v1.x + w2 * v2.x + w3 * v3.x;
        acc.y += w0 * v0.y + w1 * v1.y + w2 * v2.y + w3 * v3.y;
        acc.z += w0 * v0.z + w1 * v1.z + w2 * v2.z + w3 * v3.z;
        acc.w += w0 * v0.w + w1 * v1.w + w2 * v2.w + w3 * v3.w;
    }
    for (; j < end; j++) {
        int s = g_csr_src[j];
        float w = g_dinv[s];
        float4 hv = h4[(size_t)s * 32 + lane];
        acc.x += w * hv.x; acc.y += w * hv.y;
        acc.z += w * hv.z; acc.w += w * hv.w;
    }
    float4 hs = h4[(size_t)node * 32 + lane];
    float dii = di * di;
    acc.x = di * acc.x + dii * hs.x;
    acc.y = di * acc.y + dii * hs.y;
    acc.z = di * acc.z + dii * hs.z;
    acc.w = di * acc.w + dii * hs.w;

    float4 b = ((const float4*)bias)[lane];
    float v[4];
    v[0] = fmaxf(acc.x + b.x, 0.f);
    v[1] = fmaxf(acc.y + b.y, 0.f);
    v[2] = fmaxf(acc.z + b.z, 0.f);
    v[3] = fmaxf(acc.w + b.w, 0.f);

    size_t base = (size_t)node * EMB_W + col_off + lane * 4;
    #pragma unroll
    for (int c = 0; c < 4; c += 2) {
        __nv_bfloat16 h0 = __float2bfloat16_rn(v[c]);
        __nv_bfloat16 h1 = __float2bfloat16_rn(v[c + 1]);
        __nv_bfloat162 p; p.x = h0; p.y = h1;
        *(__nv_bfloat162*)(g_e0 + base + c) = p;
        __nv_bfloat162 q;
        q.x = __float2bfloat16_rn(v[c]     - __bfloat162float(h0));
        q.y = __float2bfloat16_rn(v[c + 1] - __bfloat162float(h1));
        *(__nv_bfloat162*)(g_e1 + base + c) = q;
    }
}

// ---------------------------------------------------------------------------
// Launch (R8/R13 structure)
// ---------------------------------------------------------------------------
extern "C" void kernel_launch(void* const* d_in, const int* in_sizes, int n_in,
                              void* d_out, int out_size)
{
    const float* x   = (const float*)d_in[0];
    const int*   ei  = (const int*)  d_in[1];
    const float* pre_w = (const float*)d_in[2];
    const float* pre_b = (const float*)d_in[3];
    const float* conv_w[4] = { (const float*)d_in[4], (const float*)d_in[6],
                               (const float*)d_in[8], (const float*)d_in[10] };
    const float* conv_b[4] = { (const float*)d_in[5], (const float*)d_in[7],
                               (const float*)d_in[9], (const float*)d_in[11] };
    const float* pw1 = (const float*)d_in[12]; const float* pb1 = (const float*)d_in[13];
    const float* pw2 = (const float*)d_in[14]; const float* pb2 = (const float*)d_in[15];
    const float* pw3 = (const float*)d_in[16]; const float* pb3 = (const float*)d_in[17];
    const float* pw4 = (const float*)d_in[18]; const float* pb4 = (const float*)d_in[19];
    float* out = (float*)d_out;

    __nv_bfloat16 *xa0, *xa1, *e0, *e1, *t1a, *t1b, *t2a, *t2b, *t3a, *t3b, *w0, *w1;
    float* hp;
    cudaGetSymbolAddress((void**)&xa0, g_xa0);
    cudaGetSymbolAddress((void**)&xa1, g_xa1);
    cudaGetSymbolAddress((void**)&e0,  g_e0);
    cudaGetSymbolAddress((void**)&e1,  g_e1);
    cudaGetSymbolAddress((void**)&t1a, g_t1a);
    cudaGetSymbolAddress((void**)&t1b, g_t1b);
    cudaGetSymbolAddress((void**)&t2a, g_t2a);
    cudaGetSymbolAddress((void**)&t2b, g_t2b);
    cudaGetSymbolAddress((void**)&t3a, g_t3a);
    cudaGetSymbolAddress((void**)&t3b, g_t3b);
    cudaGetSymbolAddress((void**)&w0,  g_w0);
    cudaGetSymbolAddress((void**)&w1,  g_w1);
    cudaGetSymbolAddress((void**)&hp,  g_h);

    cudaFuncSetAttribute(k_mma_gemm, cudaFuncAttributeMaxDynamicSharedMemorySize, GEMM_SMEM);

    static cudaStream_t s_side = nullptr;
    static cudaEvent_t  s_ev1 = nullptr, s_ev2 = nullptr;
    if (s_side == nullptr) {
        cudaStreamCreateWithFlags(&s_side, cudaStreamNonBlocking);
        cudaEventCreateWithFlags(&s_ev1, cudaEventDisableTiming);
        cudaEventCreateWithFlags(&s_ev2, cudaEventDisableTiming);
    }

    const int TB = 256;
    const int nodeBlocks = (NN + TB - 1) / TB;
    const int edgeBlocks = (NE + TB - 1) / TB;
    const size_t woff[9] = { 0, 16384, 32768, 65536, 114688, 180224, 262144, 278528, 311296 };

    // Fork: CSR build on side stream.
    cudaEventRecord(s_ev1, 0);
    cudaStreamWaitEvent(s_side, s_ev1, 0);
    k_zero_deg<<<nodeBlocks, TB, 0, s_side>>>();
    k_hist<<<edgeBlocks, TB, 0, s_side>>>(ei);
    k_scan1<<<SCAN_B, 1024, 0, s_side>>>();
    k_scan2<<<1, 128, 0, s_side>>>();
    k_scan3<<<SCAN_B, 1024, 0, s_side>>>();
    k_scatter<<<edgeBlocks, TB, 0, s_side>>>(ei);
    cudaEventRecord(s_ev2, s_side);

    // Main stream: fused prep+cvt, then GEMMs
    k_prep_cvt<<<1344 + CVT_BLOCKS, 256>>>(x, pre_w, conv_w[0], conv_w[1], conv_w[2],
                                           conv_w[3], pw1, pw2, pw3, pw4);

    k_mma_gemm<<<GRID_M, 128, GEMM_SMEM>>>(xa0, xa1, HID, HID, w0 + woff[0], w1 + woff[0],
                                           pre_b, 0, 1, nullptr, 0, e0, e1, EMB_W, 0, NN);
    k_mma_gemm<<<GRID_M, 128, GEMM_SMEM>>>(e0, e1, EMB_W, HID, w0 + woff[1], w1 + woff[1],
                                           nullptr, 0, 0, hp, HID,
                                           nullptr, nullptr, 0, 0, NN);

    // Join: aggregation needs CSR
    cudaStreamWaitEvent(0, s_ev2, 0);
    k_aggregate<<<(NN + 7) / 8, 256>>>(conv_b[0], HID);

    // Layers 2-4
    for (int l = 1; l < 4; l++) {
        int K = HID * (l + 1);
        k_mma_gemm<<<GRID_M, 128, GEMM_SMEM>>>(e0, e1, EMB_W, K,
                                               w0 + woff[1 + l], w1 + woff[1 + l],
                                               nullptr, 0, 0, hp, HID,
                                               nullptr, nullptr, 0, 0, NN);
        k_aggregate<<<(NN + 7) / 8, 256>>>(conv_b[l], K);
    }

    // post_mp
    k_mma_gemm<<<GRID_M, 128, GEMM_SMEM>>>(e0, e1, EMB_W, EMB_W, w0 + woff[5], w1 + woff[5],
                                           pb1, 2, 1, nullptr, 0, t1a, t1b, HID, 0, NN);
    k_mma_gemm<<<GRID_M, 128, GEMM_SMEM>>>(t1a, t1b, HID, HID, w0 + woff[6], w1 + woff[6],
                                           pb2, 1, 1, nullptr, 0, t2a, t2b, HID, 0, NN);
    k_mma_gemm<<<dim3(GRID_M, 2), 128, GEMM_SMEM>>>(t2a, t2b, HID, HID,
                                                    w0 + woff[7], w1 + woff[7],
                                                    pb3, 1, 1, nullptr, 0,
                                                    t3a, t3b, 256, 0, NN);
    k_mma_gemm<<<GRID_M, 128, GEMM_SMEM>>>(t3a, t3b, 256, 256, w0 + woff[8], w1 + woff[8],
                                           pb4, 0, 0, out, HID, nullptr, nullptr, 0, 0, NN);
}